// round 13
// baseline (speedup 1.0000x reference)
#include <cuda_runtime.h>
#include <cuda_fp16.h>
#include <math.h>
#include <stdint.h>

// Problem dims
#define B_  128
#define T_  256
#define C_  384
#define H_  6
#define D_  64
#define BT  (B_*T_)      // 32768 rows
#define FF  (4*C_)       // 1536
#define QKVW (3*C_)      // 1152

// ---------------- scratch (device globals; allocation-free) ----------------
__device__ __half g_h1  [BT*C_];        // LN1 out (fp16)
__device__ __half g_qkv [BT*QKVW];      // q|k|v per row (fp16)
__device__ __half g_attn[BT*C_];        // attention out (fp16)
__device__ float  g_y1  [BT*C_];        // x + attn@Wp + bp
__device__ __half g_h2  [BT*C_];        // LN2 out (fp16)
__device__ __half g_mid [BT*FF];        // relu(h2@W1+b1) (fp16)
__device__ __half g_WqkvT[QKVW*C_];     // QKV weights [n][k] fp16
__device__ __half g_WpT [C_*C_];        // Wp  [n][k] fp16
__device__ __half g_W1T [FF*C_];        // W1  [n][k] fp16
__device__ __half g_W2T [C_*FF];        // W2  [n][k] fp16

// ---------------- PTX helpers ----------------
__device__ __forceinline__ void ldsm_x4(uint32_t* r, uint32_t addr) {
    asm volatile("ldmatrix.sync.aligned.m8n8.x4.shared.b16 {%0,%1,%2,%3}, [%4];"
                 : "=r"(r[0]), "=r"(r[1]), "=r"(r[2]), "=r"(r[3]) : "r"(addr));
}
__device__ __forceinline__ void ldsm_x4t(uint32_t* r, uint32_t addr) {
    asm volatile("ldmatrix.sync.aligned.m8n8.x4.trans.shared.b16 {%0,%1,%2,%3}, [%4];"
                 : "=r"(r[0]), "=r"(r[1]), "=r"(r[2]), "=r"(r[3]) : "r"(addr));
}
__device__ __forceinline__ void ldsm_x2(uint32_t* r, uint32_t addr) {
    asm volatile("ldmatrix.sync.aligned.m8n8.x2.shared.b16 {%0,%1}, [%2];"
                 : "=r"(r[0]), "=r"(r[1]) : "r"(addr));
}
__device__ __forceinline__ void mma_f16(float* c, const uint32_t* a, const uint32_t* b) {
    asm volatile("mma.sync.aligned.m16n8k16.row.col.f32.f16.f16.f32 "
                 "{%0,%1,%2,%3}, {%4,%5,%6,%7}, {%8,%9}, {%0,%1,%2,%3};"
                 : "+f"(c[0]), "+f"(c[1]), "+f"(c[2]), "+f"(c[3])
                 : "r"(a[0]), "r"(a[1]), "r"(a[2]), "r"(a[3]), "r"(b[0]), "r"(b[1]));
}
// fp16-accumulator variant: C fragment = 2 b32 regs (4 packed halves)
__device__ __forceinline__ void mma_f16h(uint32_t* c, const uint32_t* a, const uint32_t* b) {
    asm volatile("mma.sync.aligned.m16n8k16.row.col.f16.f16.f16.f16 "
                 "{%0,%1}, {%2,%3,%4,%5}, {%6,%7}, {%0,%1};"
                 : "+r"(c[0]), "+r"(c[1])
                 : "r"(a[0]), "r"(a[1]), "r"(a[2]), "r"(a[3]), "r"(b[0]), "r"(b[1]));
}
__device__ __forceinline__ uint32_t pack_h2(float lo, float hi) {
    uint32_t r;
    asm("cvt.rn.f16x2.f32 %0, %1, %2;" : "=r"(r) : "f"(hi), "f"(lo));
    return r;
}
__device__ __forceinline__ void cp16(uint32_t dst, const void* src) {
    asm volatile("cp.async.cg.shared.global [%0], [%1], 16;" :: "r"(dst), "l"(src));
}
#define CP_COMMIT() asm volatile("cp.async.commit_group;" ::: "memory")

// ---------------- LayerNorm: one warp per row of 384, fp16 out ----------------
__global__ void ln_kernel(const float* __restrict__ x, const float* __restrict__ g,
                          const float* __restrict__ beta, __half* __restrict__ out)
{
    int row  = blockIdx.x * 4 + (threadIdx.x >> 5);
    int lane = threadIdx.x & 31;
    const float4* xr = (const float4*)(x + (size_t)row * C_);

    float4 v[3];
    float s = 0.f, ss = 0.f;
    #pragma unroll
    for (int i = 0; i < 3; i++) {
        v[i] = xr[lane + i * 32];
        s  += v[i].x + v[i].y + v[i].z + v[i].w;
        ss += v[i].x*v[i].x + v[i].y*v[i].y + v[i].z*v[i].z + v[i].w*v[i].w;
    }
    #pragma unroll
    for (int o = 16; o > 0; o >>= 1) {
        s  += __shfl_xor_sync(0xffffffffu, s,  o);
        ss += __shfl_xor_sync(0xffffffffu, ss, o);
    }
    float mean = s * (1.0f / C_);
    float var  = ss * (1.0f / C_) - mean * mean;
    float rstd = rsqrtf(var + 1e-5f);

    __half* orow = out + (size_t)row * C_;
    #pragma unroll
    for (int i = 0; i < 3; i++) {
        int c = (lane + i * 32) * 4;
        float4 gg = *(const float4*)(g + c);
        float4 bb = *(const float4*)(beta + c);
        float e0 = (v[i].x - mean) * rstd * gg.x + bb.x;
        float e1 = (v[i].y - mean) * rstd * gg.y + bb.y;
        float e2 = (v[i].z - mean) * rstd * gg.z + bb.z;
        float e3 = (v[i].w - mean) * rstd * gg.w + bb.w;
        *(__half2*)(orow + c)     = __floats2half2_rn(e0, e1);
        *(__half2*)(orow + c + 2) = __floats2half2_rn(e2, e3);
    }
}

// ------------- repack Wq/Wk/Wv (H,C,Dh) -> WqkvT[n][k] fp16, n = which*384+h*64+d ----
__global__ void repackT_kernel(const float* __restrict__ Wq, const float* __restrict__ Wk,
                               const float* __restrict__ Wv, __half* __restrict__ WqkvT)
{
    int idx = blockIdx.x * blockDim.x + threadIdx.x;
    if (idx >= QKVW * C_) return;
    int n = idx / C_;
    int k = idx % C_;
    int which = n / C_;
    int nn = n % C_;
    int h = nn / D_, d = nn % D_;
    const float* W = (which == 0) ? Wq : (which == 1) ? Wk : Wv;
    WqkvT[idx] = __float2half_rn(W[(size_t)h * C_ * D_ + (size_t)k * D_ + d]);
}

// ---------------- tiled transpose: W[K][N] fp32 -> Wt[N][K] fp16 ----------------
__global__ void transpose_kernel(const float* __restrict__ W, __half* __restrict__ Wt,
                                 int K, int N)
{
    __shared__ float tile[32][33];
    int kb = blockIdx.x * 32, nb = blockIdx.y * 32;
    int tx = threadIdx.x, ty = threadIdx.y;   // (32, 8)
    #pragma unroll
    for (int i = ty; i < 32; i += 8)
        tile[i][tx] = W[(size_t)(kb + i) * N + nb + tx];
    __syncthreads();
    #pragma unroll
    for (int i = ty; i < 32; i += 8)
        Wt[(size_t)(nb + i) * K + kb + tx] = __float2half_rn(tile[tx][i]);
}

// --------- fp16 tensor-core GEMM: C = A[MxK] * Bt[NxK]^T (+bias)(+res)(+relu) -------
// BM=128 BN=128 BK=32, 256 threads, 3-stage cp.async pipeline.
// fp16 accumulators within each 128-deep K-chunk, promoted to fp32 between chunks.
template<int EPI, typename OutT>
__global__ void __launch_bounds__(256)
mma_gemm(const __half* __restrict__ A, const __half* __restrict__ Bt,
         const float* __restrict__ bias, const float* __restrict__ res,
         OutT* __restrict__ C, int M, int N, int K)
{
    const int ROWB = 80;                // bytes per padded smem row
    const int TILE = 128 * ROWB;        // 10240
    const int STG  = 2 * TILE;          // A+B per stage = 20480
    extern __shared__ __align__(128) char sbuf[];    // 3 * STG = 61440

    uint32_t sbase = (uint32_t)__cvta_generic_to_shared(sbuf);
    int tid = threadIdx.x, warp = tid >> 5, lane = tid & 31;
    int wm = (warp >> 2) * 64;
    int wn = (warp & 3) * 32;
    int m0 = blockIdx.y * 128, n0 = blockIdx.x * 128;
    int nk = K >> 5;

    float acc[4][4][4];        // persistent fp32 accumulators
    uint32_t hacc[4][4][2];    // per-chunk packed fp16 accumulators
    #pragma unroll
    for (int i = 0; i < 4; i++)
        #pragma unroll
        for (int j = 0; j < 4; j++) {
            #pragma unroll
            for (int r = 0; r < 4; r++) acc[i][j][r] = 0.f;
            hacc[i][j][0] = 0u; hacc[i][j][1] = 0u;
        }

    uint32_t arow_off[4], brow_off[4];
    #pragma unroll
    for (int mt = 0; mt < 4; mt++)
        arow_off[mt] = (uint32_t)((wm + mt * 16 + (lane & 15)) * ROWB + ((lane & 16) ? 16 : 0));
    #pragma unroll
    for (int nt = 0; nt < 4; nt++)
        brow_off[nt] = (uint32_t)((wn + nt * 8 + (lane & 7)) * ROWB + ((lane & 8) ? 16 : 0));

    auto stage = [&](int t, int buf) {
        int k0 = t << 5;
        uint32_t a_dst = sbase + (uint32_t)buf * STG;
        uint32_t b_dst = a_dst + TILE;
        #pragma unroll
        for (int i = 0; i < 2; i++) {
            int idx = tid + i * 256;
            int r = idx >> 2, cg = idx & 3;
            cp16(a_dst + (uint32_t)(r * ROWB + cg * 16),
                 A + (size_t)(m0 + r) * K + k0 + cg * 8);
        }
        #pragma unroll
        for (int i = 0; i < 2; i++) {
            int idx = tid + i * 256;
            int r = idx >> 2, cg = idx & 3;
            cp16(b_dst + (uint32_t)(r * ROWB + cg * 16),
                 Bt + (size_t)(n0 + r) * K + k0 + cg * 8);
        }
    };

    auto compute = [&](int buf) {
        uint32_t a_base = sbase + (uint32_t)buf * STG;
        uint32_t b_base = a_base + TILE;
        #pragma unroll
        for (int ks = 0; ks < 2; ks++) {
            uint32_t afr[4][4];
            #pragma unroll
            for (int mt = 0; mt < 4; mt++)
                ldsm_x4(afr[mt], a_base + arow_off[mt] + ks * 32u);
            uint32_t bfr[4][2];
            #pragma unroll
            for (int nt = 0; nt < 4; nt++)
                ldsm_x2(bfr[nt], b_base + brow_off[nt] + ks * 32u);
            #pragma unroll
            for (int mt = 0; mt < 4; mt++)
                #pragma unroll
                for (int nt = 0; nt < 4; nt++)
                    mma_f16h(hacc[mt][nt], afr[mt], bfr[nt]);
        }
    };

    auto promote = [&]() {
        #pragma unroll
        for (int mt = 0; mt < 4; mt++)
            #pragma unroll
            for (int nt = 0; nt < 4; nt++) {
                float2 lo = __half22float2(*(__half2*)&hacc[mt][nt][0]);
                float2 hi = __half22float2(*(__half2*)&hacc[mt][nt][1]);
                acc[mt][nt][0] += lo.x; acc[mt][nt][1] += lo.y;
                acc[mt][nt][2] += hi.x; acc[mt][nt][3] += hi.y;
                hacc[mt][nt][0] = 0u; hacc[mt][nt][1] = 0u;
            }
    };

    // prologue: 2 stages in flight
    stage(0, 0); CP_COMMIT();
    stage(1, 1); CP_COMMIT();

    int buf = 0;
    for (int t = 0; t < nk; t++) {
        if (t < nk - 1) asm volatile("cp.async.wait_group 1;" ::: "memory");
        else            asm volatile("cp.async.wait_group 0;" ::: "memory");
        __syncthreads();
        if (t + 2 < nk) {
            int nb = buf + 2; if (nb >= 3) nb -= 3;
            stage(t + 2, nb);
            CP_COMMIT();
        }
        compute(buf);
        if ((t & 3) == 3 || t == nk - 1) promote();
        if (++buf == 3) buf = 0;
    }

    #pragma unroll
    for (int mt = 0; mt < 4; mt++) {
        int row = m0 + wm + mt * 16 + (lane >> 2);
        #pragma unroll
        for (int nt = 0; nt < 4; nt++) {
            int col = n0 + wn + nt * 8 + 2 * (lane & 3);
            float v0 = acc[mt][nt][0], v1 = acc[mt][nt][1];
            float v2 = acc[mt][nt][2], v3 = acc[mt][nt][3];
            if (EPI >= 1) {
                float b0 = bias[col], b1 = bias[col + 1];
                v0 += b0; v1 += b1; v2 += b0; v3 += b1;
            }
            if (EPI == 2) {
                float2 r0 = *(const float2*)(res + (size_t)row * N + col);
                float2 r1 = *(const float2*)(res + (size_t)(row + 8) * N + col);
                v0 += r0.x; v1 += r0.y; v2 += r1.x; v3 += r1.y;
            }
            if (EPI == 3) {
                v0 = fmaxf(v0, 0.f); v1 = fmaxf(v1, 0.f);
                v2 = fmaxf(v2, 0.f); v3 = fmaxf(v3, 0.f);
            }
            if (sizeof(OutT) == 4) {
                *(float2*)((float*)C + (size_t)row * N + col)       = make_float2(v0, v1);
                *(float2*)((float*)C + (size_t)(row + 8) * N + col) = make_float2(v2, v3);
            } else {
                *(__half2*)((__half*)C + (size_t)row * N + col)       = __floats2half2_rn(v0, v1);
                *(__half2*)((__half*)C + (size_t)(row + 8) * N + col) = __floats2half2_rn(v2, v3);
            }
        }
    }
}

// ---------------- MMA flash attention (causal), 64-key chunks ----------------
// grid = (2 q-tiles, B*H). 256 threads = 8 warps x 16 query rows. 2 CTAs/SM.
#define ASTR 72   // smem row stride in halves (144B: conflict-free ldmatrix)
__global__ void __launch_bounds__(256, 2)
fattn_kernel(const __half* __restrict__ qkv, __half* __restrict__ out)
{
    extern __shared__ __half sm[];
    __half* Qs = sm;                  // [128][ASTR]
    __half* Ks = sm + 128 * ASTR;
    __half* Vs = Ks + 128 * ASTR;

    int qt = blockIdx.x;              // 0/1
    int bh = blockIdx.y;
    int b = bh / H_, h = bh % H_;
    int tid = threadIdx.x, warp = tid >> 5, lane = tid & 31;
    int wm = warp * 16;
    int q0 = qt * 128;
    const __half* base = qkv + (size_t)b * T_ * QKVW + (size_t)h * D_;

    uint32_t qs_a = (uint32_t)__cvta_generic_to_shared(Qs);
    uint32_t ks_a = (uint32_t)__cvta_generic_to_shared(Ks);
    uint32_t vs_a = (uint32_t)__cvta_generic_to_shared(Vs);

    // load Q tile (128 x 64 halves)
    for (int i = tid; i < 128 * 8; i += 256) {
        int r = i >> 3, c = i & 7;
        *(float4*)(Qs + r * ASTR + c * 8) =
            *(const float4*)(base + (size_t)(q0 + r) * QKVW + c * 8);
    }

    float mlo = -1e30f, mhi = -1e30f, llo = 0.f, lhi = 0.f;
    float oacc[8][4];
    #pragma unroll
    for (int j = 0; j < 8; j++)
        #pragma unroll
        for (int e = 0; e < 4; e++) oacc[j][e] = 0.f;

    const float scale = 0.05103103630798287f;   // 1/sqrt(384)
    int qlo_g = q0 + wm + (lane >> 2);
    int qhi_g = qlo_g + 8;

    uint32_t qf[4][4];

    for (int kt = 0; kt <= qt; kt++) {
        int k0 = kt * 128;
        bool diag = (kt == qt);
        if (kt > 0) __syncthreads();
        for (int i = tid; i < 128 * 8; i += 256) {
            int r = i >> 3, c = i & 7;
            size_t roff = (size_t)(k0 + r) * QKVW + c * 8;
            *(float4*)(Ks + r * ASTR + c * 8) = *(const float4*)(base + C_  + roff);
            *(float4*)(Vs + r * ASTR + c * 8) = *(const float4*)(base + 2*C_ + roff);
        }
        __syncthreads();

        if (kt == 0) {
            #pragma unroll
            for (int kk = 0; kk < 4; kk++)
                ldsm_x4(qf[kk], qs_a + (uint32_t)(((wm + (lane & 15)) * ASTR
                                     + kk * 16 + ((lane >> 4) & 1) * 8) * 2));
        }

        #pragma unroll
        for (int c2 = 0; c2 < 2; c2++) {
            if (diag && c2 == 1 && wm < 64) continue;   // fully-masked chunk
            int kc0 = k0 + c2 * 64;

            float sacc[8][4];
            #pragma unroll
            for (int j = 0; j < 8; j++)
                #pragma unroll
                for (int e = 0; e < 4; e++) sacc[j][e] = 0.f;

            #pragma unroll
            for (int kk = 0; kk < 4; kk++) {
                #pragma unroll
                for (int j2 = 0; j2 < 4; j2++) {
                    uint32_t kb[4];
                    ldsm_x4(kb, ks_a + (uint32_t)(((c2 * 64 + j2 * 16 + ((lane >> 4) & 1) * 8 + (lane & 7)) * ASTR
                                       + kk * 16 + ((lane >> 3) & 1) * 8) * 2));
                    mma_f16(sacc[2*j2],     qf[kk], kb);
                    mma_f16(sacc[2*j2 + 1], qf[kk], kb + 2);
                }
            }

            float rmlo = -1e30f, rmhi = -1e30f;
            #pragma unroll
            for (int j = 0; j < 8; j++) {
                int key = kc0 + 8 * j + 2 * (lane & 3);
                #pragma unroll
                for (int e = 0; e < 2; e++) {
                    float s = sacc[j][e] * scale;
                    if (diag && (key + e > qlo_g)) s = -1e30f;
                    sacc[j][e] = s;
                    rmlo = fmaxf(rmlo, s);
                }
                #pragma unroll
                for (int e = 2; e < 4; e++) {
                    float s = sacc[j][e] * scale;
                    if (diag && (key + e - 2 > qhi_g)) s = -1e30f;
                    sacc[j][e] = s;
                    rmhi = fmaxf(rmhi, s);
                }
            }
            rmlo = fmaxf(rmlo, __shfl_xor_sync(0xffffffffu, rmlo, 1));
            rmlo = fmaxf(rmlo, __shfl_xor_sync(0xffffffffu, rmlo, 2));
            rmhi = fmaxf(rmhi, __shfl_xor_sync(0xffffffffu, rmhi, 1));
            rmhi = fmaxf(rmhi, __shfl_xor_sync(0xffffffffu, rmhi, 2));

            float mnlo = fmaxf(mlo, rmlo), mnhi = fmaxf(mhi, rmhi);
            float elo = __expf(mlo - mnlo), ehi = __expf(mhi - mnhi);
            mlo = mnlo; mhi = mnhi;

            float slo = 0.f, shi = 0.f;
            #pragma unroll
            for (int j = 0; j < 8; j++) {
                float p0 = __expf(sacc[j][0] - mnlo);
                float p1 = __expf(sacc[j][1] - mnlo);
                float p2 = __expf(sacc[j][2] - mnhi);
                float p3 = __expf(sacc[j][3] - mnhi);
                sacc[j][0] = p0; sacc[j][1] = p1; sacc[j][2] = p2; sacc[j][3] = p3;
                slo += p0 + p1; shi += p2 + p3;
            }
            slo += __shfl_xor_sync(0xffffffffu, slo, 1);
            slo += __shfl_xor_sync(0xffffffffu, slo, 2);
            shi += __shfl_xor_sync(0xffffffffu, shi, 1);
            shi += __shfl_xor_sync(0xffffffffu, shi, 2);
            llo = llo * elo + slo;
            lhi = lhi * ehi + shi;

            #pragma unroll
            for (int j = 0; j < 8; j++) {
                oacc[j][0] *= elo; oacc[j][1] *= elo;
                oacc[j][2] *= ehi; oacc[j][3] *= ehi;
            }

            #pragma unroll
            for (int kk2 = 0; kk2 < 4; kk2++) {
                uint32_t pa[4];
                pa[0] = pack_h2(sacc[2*kk2][0],   sacc[2*kk2][1]);
                pa[1] = pack_h2(sacc[2*kk2][2],   sacc[2*kk2][3]);
                pa[2] = pack_h2(sacc[2*kk2+1][0], sacc[2*kk2+1][1]);
                pa[3] = pack_h2(sacc[2*kk2+1][2], sacc[2*kk2+1][3]);
                #pragma unroll
                for (int j2 = 0; j2 < 4; j2++) {
                    uint32_t vb[4];
                    ldsm_x4t(vb, vs_a + (uint32_t)(((c2 * 64 + kk2 * 16 + ((lane >> 3) & 1) * 8 + (lane & 7)) * ASTR
                                        + j2 * 16 + ((lane >> 4) & 1) * 8) * 2));
                    mma_f16(oacc[2*j2],     pa, vb);
                    mma_f16(oacc[2*j2 + 1], pa, vb + 2);
                }
            }
        }
    }

    float ilo = 1.f / llo, ihi = 1.f / lhi;
    size_t rlo = (size_t)(b * T_ + qlo_g) * C_ + (size_t)h * D_;
    size_t rhi = (size_t)(b * T_ + qhi_g) * C_ + (size_t)h * D_;
    #pragma unroll
    for (int j = 0; j < 8; j++) {
        int col = 8 * j + 2 * (lane & 3);
        *(__half2*)(out + rlo + col) = __floats2half2_rn(oacc[j][0] * ilo, oacc[j][1] * ilo);
        *(__half2*)(out + rhi + col) = __floats2half2_rn(oacc[j][2] * ihi, oacc[j][3] * ihi);
    }
}

// ---------------- launch ----------------
extern "C" void kernel_launch(void* const* d_in, const int* in_sizes, int n_in,
                              void* d_out, int out_size)
{
    const float* x   = (const float*)d_in[0];
    const float* Wq  = (const float*)d_in[1];
    const float* Wk  = (const float*)d_in[2];
    const float* Wv  = (const float*)d_in[3];
    const float* Wp  = (const float*)d_in[4];
    const float* bp  = (const float*)d_in[5];
    const float* W1  = (const float*)d_in[6];
    const float* b1  = (const float*)d_in[7];
    const float* W2  = (const float*)d_in[8];
    const float* b2  = (const float*)d_in[9];
    const float* g1  = (const float*)d_in[10];
    const float* be1 = (const float*)d_in[11];
    const float* g2  = (const float*)d_in[12];
    const float* be2 = (const float*)d_in[13];
    float* out = (float*)d_out;

    __half *h1, *qkv, *attn, *h2, *mid, *WqkvT, *WpT, *W1T, *W2T;
    float *y1;
    cudaGetSymbolAddress((void**)&h1,    g_h1);
    cudaGetSymbolAddress((void**)&qkv,   g_qkv);
    cudaGetSymbolAddress((void**)&attn,  g_attn);
    cudaGetSymbolAddress((void**)&y1,    g_y1);
    cudaGetSymbolAddress((void**)&h2,    g_h2);
    cudaGetSymbolAddress((void**)&mid,   g_mid);
    cudaGetSymbolAddress((void**)&WqkvT, g_WqkvT);
    cudaGetSymbolAddress((void**)&WpT,   g_WpT);
    cudaGetSymbolAddress((void**)&W1T,   g_W1T);
    cudaGetSymbolAddress((void**)&W2T,   g_W2T);

    static const int FATTN_SMEM = 3 * 128 * ASTR * (int)sizeof(__half);   // 55296
    static const int GEMM_SMEM  = 3 * 2 * 128 * 80;                        // 61440
    cudaFuncSetAttribute(fattn_kernel, cudaFuncAttributeMaxDynamicSharedMemorySize, FATTN_SMEM);
    cudaFuncSetAttribute(mma_gemm<0, __half>, cudaFuncAttributeMaxDynamicSharedMemorySize, GEMM_SMEM);
    cudaFuncSetAttribute(mma_gemm<2, float>,  cudaFuncAttributeMaxDynamicSharedMemorySize, GEMM_SMEM);
    cudaFuncSetAttribute(mma_gemm<3, __half>, cudaFuncAttributeMaxDynamicSharedMemorySize, GEMM_SMEM);

    // 1. LN1 (fp16 out)
    ln_kernel<<<BT / 4, 128>>>(x, g1, be1, h1);

    // 2. weight repack/transpose to fp16 [N][K]
    repackT_kernel<<<(QKVW * C_ + 255) / 256, 256>>>(Wq, Wk, Wv, WqkvT);
    transpose_kernel<<<dim3(C_ / 32, C_ / 32), dim3(32, 8)>>>(Wp, WpT, C_, C_);
    transpose_kernel<<<dim3(C_ / 32, FF / 32), dim3(32, 8)>>>(W1, W1T, C_, FF);
    transpose_kernel<<<dim3(FF / 32, C_ / 32), dim3(32, 8)>>>(W2, W2T, FF, C_);

    // 3. qkv = h1 @ Wqkv           [32768 x 1152] fp16
    mma_gemm<0, __half><<<dim3(QKVW / 128, BT / 128), 256, GEMM_SMEM>>>(h1, WqkvT, nullptr, nullptr, qkv, BT, QKVW, C_);

    // 4. MMA flash attention       -> attn [32768 x 384] fp16
    fattn_kernel<<<dim3(2, B_ * H_), 256, FATTN_SMEM>>>(qkv, attn);

    // 5. y1 = x + attn @ Wp + bp   fp32
    mma_gemm<2, float><<<dim3(C_ / 128, BT / 128), 256, GEMM_SMEM>>>(attn, WpT, bp, x, y1, BT, C_, C_);

    // 6. LN2 (fp16 out)
    ln_kernel<<<BT / 4, 128>>>(y1, g2, be2, h2);

    // 7. mid = relu(h2 @ W1 + b1)  [32768 x 1536] fp16
    mma_gemm<3, __half><<<dim3(FF / 128, BT / 128), 256, GEMM_SMEM>>>(h2, W1T, b1, nullptr, mid, BT, FF, C_);

    // 8. out = y1 + mid @ W2 + b2  fp32
    mma_gemm<2, float><<<dim3(C_ / 128, BT / 128), 256, GEMM_SMEM>>>(mid, W2T, b2, y1, out, BT, C_, FF);
}

// round 14
// speedup vs baseline: 1.1246x; 1.1246x over previous
#include <cuda_runtime.h>
#include <cuda_fp16.h>
#include <math.h>
#include <stdint.h>

// Problem dims
#define B_  128
#define T_  256
#define C_  384
#define H_  6
#define D_  64
#define BT  (B_*T_)      // 32768 rows
#define FF  (4*C_)       // 1536
#define QKVW (3*C_)      // 1152

// ---------------- scratch (device globals; allocation-free) ----------------
__device__ __half g_h1  [BT*C_];        // LN1 out (fp16)
__device__ __half g_qkv [BT*QKVW];      // q|k|v per row (fp16)
__device__ __half g_attn[BT*C_];        // attention out (fp16)
__device__ float  g_y1  [BT*C_];        // x + attn@Wp + bp
__device__ __half g_h2  [BT*C_];        // LN2 out (fp16)
__device__ __half g_mid [BT*FF];        // relu(h2@W1+b1) (fp16)
__device__ __half g_WqkvT[QKVW*C_];     // QKV weights [n][k] fp16
__device__ __half g_WpT [C_*C_];        // Wp  [n][k] fp16
__device__ __half g_W1T [FF*C_];        // W1  [n][k] fp16
__device__ __half g_W2T [C_*FF];        // W2  [n][k] fp16

// ---------------- PTX helpers ----------------
__device__ __forceinline__ void ldsm_x4(uint32_t* r, uint32_t addr) {
    asm volatile("ldmatrix.sync.aligned.m8n8.x4.shared.b16 {%0,%1,%2,%3}, [%4];"
                 : "=r"(r[0]), "=r"(r[1]), "=r"(r[2]), "=r"(r[3]) : "r"(addr));
}
__device__ __forceinline__ void ldsm_x4t(uint32_t* r, uint32_t addr) {
    asm volatile("ldmatrix.sync.aligned.m8n8.x4.trans.shared.b16 {%0,%1,%2,%3}, [%4];"
                 : "=r"(r[0]), "=r"(r[1]), "=r"(r[2]), "=r"(r[3]) : "r"(addr));
}
__device__ __forceinline__ void ldsm_x2(uint32_t* r, uint32_t addr) {
    asm volatile("ldmatrix.sync.aligned.m8n8.x2.shared.b16 {%0,%1}, [%2];"
                 : "=r"(r[0]), "=r"(r[1]) : "r"(addr));
}
__device__ __forceinline__ void mma_f16(float* c, const uint32_t* a, const uint32_t* b) {
    asm volatile("mma.sync.aligned.m16n8k16.row.col.f32.f16.f16.f32 "
                 "{%0,%1,%2,%3}, {%4,%5,%6,%7}, {%8,%9}, {%0,%1,%2,%3};"
                 : "+f"(c[0]), "+f"(c[1]), "+f"(c[2]), "+f"(c[3])
                 : "r"(a[0]), "r"(a[1]), "r"(a[2]), "r"(a[3]), "r"(b[0]), "r"(b[1]));
}
__device__ __forceinline__ uint32_t pack_h2(float lo, float hi) {
    uint32_t r;
    asm("cvt.rn.f16x2.f32 %0, %1, %2;" : "=r"(r) : "f"(hi), "f"(lo));
    return r;
}
__device__ __forceinline__ void cp16(uint32_t dst, const void* src) {
    asm volatile("cp.async.cg.shared.global [%0], [%1], 16;" :: "r"(dst), "l"(src));
}
#define CP_COMMIT() asm volatile("cp.async.commit_group;" ::: "memory")

// ---------------- LayerNorm: one warp per row of 384, fp16 out ----------------
__global__ void ln_kernel(const float* __restrict__ x, const float* __restrict__ g,
                          const float* __restrict__ beta, __half* __restrict__ out)
{
    int row  = blockIdx.x * 4 + (threadIdx.x >> 5);
    int lane = threadIdx.x & 31;
    const float4* xr = (const float4*)(x + (size_t)row * C_);

    float4 v[3];
    float s = 0.f, ss = 0.f;
    #pragma unroll
    for (int i = 0; i < 3; i++) {
        v[i] = xr[lane + i * 32];
        s  += v[i].x + v[i].y + v[i].z + v[i].w;
        ss += v[i].x*v[i].x + v[i].y*v[i].y + v[i].z*v[i].z + v[i].w*v[i].w;
    }
    #pragma unroll
    for (int o = 16; o > 0; o >>= 1) {
        s  += __shfl_xor_sync(0xffffffffu, s,  o);
        ss += __shfl_xor_sync(0xffffffffu, ss, o);
    }
    float mean = s * (1.0f / C_);
    float var  = ss * (1.0f / C_) - mean * mean;
    float rstd = rsqrtf(var + 1e-5f);

    __half* orow = out + (size_t)row * C_;
    #pragma unroll
    for (int i = 0; i < 3; i++) {
        int c = (lane + i * 32) * 4;
        float4 gg = *(const float4*)(g + c);
        float4 bb = *(const float4*)(beta + c);
        float e0 = (v[i].x - mean) * rstd * gg.x + bb.x;
        float e1 = (v[i].y - mean) * rstd * gg.y + bb.y;
        float e2 = (v[i].z - mean) * rstd * gg.z + bb.z;
        float e3 = (v[i].w - mean) * rstd * gg.w + bb.w;
        *(__half2*)(orow + c)     = __floats2half2_rn(e0, e1);
        *(__half2*)(orow + c + 2) = __floats2half2_rn(e2, e3);
    }
}

// ------------- repack Wq/Wk/Wv (H,C,Dh) -> WqkvT[n][k] fp16, n = which*384+h*64+d ----
__global__ void repackT_kernel(const float* __restrict__ Wq, const float* __restrict__ Wk,
                               const float* __restrict__ Wv, __half* __restrict__ WqkvT)
{
    int idx = blockIdx.x * blockDim.x + threadIdx.x;
    if (idx >= QKVW * C_) return;
    int n = idx / C_;
    int k = idx % C_;
    int which = n / C_;
    int nn = n % C_;
    int h = nn / D_, d = nn % D_;
    const float* W = (which == 0) ? Wq : (which == 1) ? Wk : Wv;
    WqkvT[idx] = __float2half_rn(W[(size_t)h * C_ * D_ + (size_t)k * D_ + d]);
}

// ---------------- tiled transpose: W[K][N] fp32 -> Wt[N][K] fp16 ----------------
__global__ void transpose_kernel(const float* __restrict__ W, __half* __restrict__ Wt,
                                 int K, int N)
{
    __shared__ float tile[32][33];
    int kb = blockIdx.x * 32, nb = blockIdx.y * 32;
    int tx = threadIdx.x, ty = threadIdx.y;   // (32, 8)
    #pragma unroll
    for (int i = ty; i < 32; i += 8)
        tile[i][tx] = W[(size_t)(kb + i) * N + nb + tx];
    __syncthreads();
    #pragma unroll
    for (int i = ty; i < 32; i += 8)
        Wt[(size_t)(nb + i) * K + kb + tx] = __float2half_rn(tile[tx][i]);
}

// --------- fp16 tensor-core GEMM: C = A[MxK] * Bt[NxK]^T (+bias)(+res)(+relu) -------
// BM=128 BN=128 BK=64, 256 threads, 2-stage cp.async double buffer.
// fp32 accumulators (f16-acc experiment regressed in R13; reverted).
template<int EPI, typename OutT>
__global__ void __launch_bounds__(256)
mma_gemm(const __half* __restrict__ A, const __half* __restrict__ Bt,
         const float* __restrict__ bias, const float* __restrict__ res,
         OutT* __restrict__ C, int M, int N, int K)
{
    const int ROWB = 144;               // bytes per padded smem row (64 fp16 + 16B pad)
    const int TILE = 128 * ROWB;        // 18432
    const int STG  = 2 * TILE;          // A+B per stage = 36864
    extern __shared__ __align__(128) char sbuf[];    // 2 * STG = 73728

    uint32_t sbase = (uint32_t)__cvta_generic_to_shared(sbuf);
    int tid = threadIdx.x, warp = tid >> 5, lane = tid & 31;
    int wm = (warp >> 2) * 64;
    int wn = (warp & 3) * 32;
    int m0 = blockIdx.y * 128, n0 = blockIdx.x * 128;
    int nk = K >> 6;                    // K/64 tiles

    float acc[4][4][4];
    #pragma unroll
    for (int i = 0; i < 4; i++)
        #pragma unroll
        for (int j = 0; j < 4; j++)
            #pragma unroll
            for (int r = 0; r < 4; r++) acc[i][j][r] = 0.f;

    uint32_t arow_off[4], brow_off[4];
    #pragma unroll
    for (int mt = 0; mt < 4; mt++)
        arow_off[mt] = (uint32_t)((wm + mt * 16 + (lane & 15)) * ROWB + ((lane & 16) ? 16 : 0));
    #pragma unroll
    for (int nt = 0; nt < 4; nt++)
        brow_off[nt] = (uint32_t)((wn + nt * 8 + (lane & 7)) * ROWB + ((lane & 8) ? 16 : 0));

    // stage k-tile t into buffer buf: A and B each 128 rows x 64 halves (128B/row)
    auto stage = [&](int t, int buf) {
        int k0 = t << 6;
        uint32_t a_dst = sbase + (uint32_t)buf * STG;
        uint32_t b_dst = a_dst + TILE;
        #pragma unroll
        for (int i = 0; i < 4; i++) {
            int idx = tid + i * 256;            // 1024 chunks of 16B
            int r = idx >> 3, cg = idx & 7;
            cp16(a_dst + (uint32_t)(r * ROWB + cg * 16),
                 A + (size_t)(m0 + r) * K + k0 + cg * 8);
        }
        #pragma unroll
        for (int i = 0; i < 4; i++) {
            int idx = tid + i * 256;
            int r = idx >> 3, cg = idx & 7;
            cp16(b_dst + (uint32_t)(r * ROWB + cg * 16),
                 Bt + (size_t)(n0 + r) * K + k0 + cg * 8);
        }
    };

    auto compute = [&](int buf) {
        uint32_t a_base = sbase + (uint32_t)buf * STG;
        uint32_t b_base = a_base + TILE;
        #pragma unroll
        for (int ks = 0; ks < 4; ks++) {        // four k16 steps per BK=64
            uint32_t afr[4][4];
            #pragma unroll
            for (int mt = 0; mt < 4; mt++)
                ldsm_x4(afr[mt], a_base + arow_off[mt] + ks * 32u);
            uint32_t bfr[4][2];
            #pragma unroll
            for (int nt = 0; nt < 4; nt++)
                ldsm_x2(bfr[nt], b_base + brow_off[nt] + ks * 32u);
            #pragma unroll
            for (int mt = 0; mt < 4; mt++)
                #pragma unroll
                for (int nt = 0; nt < 4; nt++)
                    mma_f16(acc[mt][nt], afr[mt], bfr[nt]);
        }
    };

    stage(0, 0);
    CP_COMMIT();
    for (int t = 0; t < nk; t++) {
        if (t + 1 < nk) {
            stage(t + 1, (t + 1) & 1);
            CP_COMMIT();
            asm volatile("cp.async.wait_group 1;" ::: "memory");
        } else {
            asm volatile("cp.async.wait_group 0;" ::: "memory");
        }
        __syncthreads();
        compute(t & 1);
        __syncthreads();
    }

    #pragma unroll
    for (int mt = 0; mt < 4; mt++) {
        int row = m0 + wm + mt * 16 + (lane >> 2);
        #pragma unroll
        for (int nt = 0; nt < 4; nt++) {
            int col = n0 + wn + nt * 8 + 2 * (lane & 3);
            float v0 = acc[mt][nt][0], v1 = acc[mt][nt][1];
            float v2 = acc[mt][nt][2], v3 = acc[mt][nt][3];
            if (EPI >= 1) {
                float b0 = bias[col], b1 = bias[col + 1];
                v0 += b0; v1 += b1; v2 += b0; v3 += b1;
            }
            if (EPI == 2) {
                float2 r0 = *(const float2*)(res + (size_t)row * N + col);
                float2 r1 = *(const float2*)(res + (size_t)(row + 8) * N + col);
                v0 += r0.x; v1 += r0.y; v2 += r1.x; v3 += r1.y;
            }
            if (EPI == 3) {
                v0 = fmaxf(v0, 0.f); v1 = fmaxf(v1, 0.f);
                v2 = fmaxf(v2, 0.f); v3 = fmaxf(v3, 0.f);
            }
            if (sizeof(OutT) == 4) {
                *(float2*)((float*)C + (size_t)row * N + col)       = make_float2(v0, v1);
                *(float2*)((float*)C + (size_t)(row + 8) * N + col) = make_float2(v2, v3);
            } else {
                *(__half2*)((__half*)C + (size_t)row * N + col)       = __floats2half2_rn(v0, v1);
                *(__half2*)((__half*)C + (size_t)(row + 8) * N + col) = __floats2half2_rn(v2, v3);
            }
        }
    }
}

// ---------------- MMA flash attention (causal), 64-key chunks ----------------
// grid = (2 q-tiles, B*H). 256 threads = 8 warps x 16 query rows. 2 CTAs/SM.
#define ASTR 72   // smem row stride in halves (144B: conflict-free ldmatrix)
__global__ void __launch_bounds__(256, 2)
fattn_kernel(const __half* __restrict__ qkv, __half* __restrict__ out)
{
    extern __shared__ __half sm[];
    __half* Qs = sm;                  // [128][ASTR]
    __half* Ks = sm + 128 * ASTR;
    __half* Vs = Ks + 128 * ASTR;

    int qt = blockIdx.x;              // 0/1
    int bh = blockIdx.y;
    int b = bh / H_, h = bh % H_;
    int tid = threadIdx.x, warp = tid >> 5, lane = tid & 31;
    int wm = warp * 16;
    int q0 = qt * 128;
    const __half* base = qkv + (size_t)b * T_ * QKVW + (size_t)h * D_;

    uint32_t qs_a = (uint32_t)__cvta_generic_to_shared(Qs);
    uint32_t ks_a = (uint32_t)__cvta_generic_to_shared(Ks);
    uint32_t vs_a = (uint32_t)__cvta_generic_to_shared(Vs);

    // load Q tile (128 x 64 halves)
    for (int i = tid; i < 128 * 8; i += 256) {
        int r = i >> 3, c = i & 7;
        *(float4*)(Qs + r * ASTR + c * 8) =
            *(const float4*)(base + (size_t)(q0 + r) * QKVW + c * 8);
    }

    float mlo = -1e30f, mhi = -1e30f, llo = 0.f, lhi = 0.f;
    float oacc[8][4];
    #pragma unroll
    for (int j = 0; j < 8; j++)
        #pragma unroll
        for (int e = 0; e < 4; e++) oacc[j][e] = 0.f;

    const float scale = 0.05103103630798287f;   // 1/sqrt(384)
    int qlo_g = q0 + wm + (lane >> 2);
    int qhi_g = qlo_g + 8;

    uint32_t qf[4][4];

    for (int kt = 0; kt <= qt; kt++) {
        int k0 = kt * 128;
        bool diag = (kt == qt);
        if (kt > 0) __syncthreads();
        for (int i = tid; i < 128 * 8; i += 256) {
            int r = i >> 3, c = i & 7;
            size_t roff = (size_t)(k0 + r) * QKVW + c * 8;
            *(float4*)(Ks + r * ASTR + c * 8) = *(const float4*)(base + C_  + roff);
            *(float4*)(Vs + r * ASTR + c * 8) = *(const float4*)(base + 2*C_ + roff);
        }
        __syncthreads();

        if (kt == 0) {
            #pragma unroll
            for (int kk = 0; kk < 4; kk++)
                ldsm_x4(qf[kk], qs_a + (uint32_t)(((wm + (lane & 15)) * ASTR
                                     + kk * 16 + ((lane >> 4) & 1) * 8) * 2));
        }

        #pragma unroll
        for (int c2 = 0; c2 < 2; c2++) {
            if (diag && c2 == 1 && wm < 64) continue;   // fully-masked chunk
            int kc0 = k0 + c2 * 64;

            float sacc[8][4];
            #pragma unroll
            for (int j = 0; j < 8; j++)
                #pragma unroll
                for (int e = 0; e < 4; e++) sacc[j][e] = 0.f;

            #pragma unroll
            for (int kk = 0; kk < 4; kk++) {
                #pragma unroll
                for (int j2 = 0; j2 < 4; j2++) {
                    uint32_t kb[4];
                    ldsm_x4(kb, ks_a + (uint32_t)(((c2 * 64 + j2 * 16 + ((lane >> 4) & 1) * 8 + (lane & 7)) * ASTR
                                       + kk * 16 + ((lane >> 3) & 1) * 8) * 2));
                    mma_f16(sacc[2*j2],     qf[kk], kb);
                    mma_f16(sacc[2*j2 + 1], qf[kk], kb + 2);
                }
            }

            float rmlo = -1e30f, rmhi = -1e30f;
            #pragma unroll
            for (int j = 0; j < 8; j++) {
                int key = kc0 + 8 * j + 2 * (lane & 3);
                #pragma unroll
                for (int e = 0; e < 2; e++) {
                    float s = sacc[j][e] * scale;
                    if (diag && (key + e > qlo_g)) s = -1e30f;
                    sacc[j][e] = s;
                    rmlo = fmaxf(rmlo, s);
                }
                #pragma unroll
                for (int e = 2; e < 4; e++) {
                    float s = sacc[j][e] * scale;
                    if (diag && (key + e - 2 > qhi_g)) s = -1e30f;
                    sacc[j][e] = s;
                    rmhi = fmaxf(rmhi, s);
                }
            }
            rmlo = fmaxf(rmlo, __shfl_xor_sync(0xffffffffu, rmlo, 1));
            rmlo = fmaxf(rmlo, __shfl_xor_sync(0xffffffffu, rmlo, 2));
            rmhi = fmaxf(rmhi, __shfl_xor_sync(0xffffffffu, rmhi, 1));
            rmhi = fmaxf(rmhi, __shfl_xor_sync(0xffffffffu, rmhi, 2));

            float mnlo = fmaxf(mlo, rmlo), mnhi = fmaxf(mhi, rmhi);
            float elo = __expf(mlo - mnlo), ehi = __expf(mhi - mnhi);
            mlo = mnlo; mhi = mnhi;

            float slo = 0.f, shi = 0.f;
            #pragma unroll
            for (int j = 0; j < 8; j++) {
                float p0 = __expf(sacc[j][0] - mnlo);
                float p1 = __expf(sacc[j][1] - mnlo);
                float p2 = __expf(sacc[j][2] - mnhi);
                float p3 = __expf(sacc[j][3] - mnhi);
                sacc[j][0] = p0; sacc[j][1] = p1; sacc[j][2] = p2; sacc[j][3] = p3;
                slo += p0 + p1; shi += p2 + p3;
            }
            slo += __shfl_xor_sync(0xffffffffu, slo, 1);
            slo += __shfl_xor_sync(0xffffffffu, slo, 2);
            shi += __shfl_xor_sync(0xffffffffu, shi, 1);
            shi += __shfl_xor_sync(0xffffffffu, shi, 2);
            llo = llo * elo + slo;
            lhi = lhi * ehi + shi;

            #pragma unroll
            for (int j = 0; j < 8; j++) {
                oacc[j][0] *= elo; oacc[j][1] *= elo;
                oacc[j][2] *= ehi; oacc[j][3] *= ehi;
            }

            #pragma unroll
            for (int kk2 = 0; kk2 < 4; kk2++) {
                uint32_t pa[4];
                pa[0] = pack_h2(sacc[2*kk2][0],   sacc[2*kk2][1]);
                pa[1] = pack_h2(sacc[2*kk2][2],   sacc[2*kk2][3]);
                pa[2] = pack_h2(sacc[2*kk2+1][0], sacc[2*kk2+1][1]);
                pa[3] = pack_h2(sacc[2*kk2+1][2], sacc[2*kk2+1][3]);
                #pragma unroll
                for (int j2 = 0; j2 < 4; j2++) {
                    uint32_t vb[4];
                    ldsm_x4t(vb, vs_a + (uint32_t)(((c2 * 64 + kk2 * 16 + ((lane >> 3) & 1) * 8 + (lane & 7)) * ASTR
                                        + j2 * 16 + ((lane >> 4) & 1) * 8) * 2));
                    mma_f16(oacc[2*j2],     pa, vb);
                    mma_f16(oacc[2*j2 + 1], pa, vb + 2);
                }
            }
        }
    }

    float ilo = 1.f / llo, ihi = 1.f / lhi;
    size_t rlo = (size_t)(b * T_ + qlo_g) * C_ + (size_t)h * D_;
    size_t rhi = (size_t)(b * T_ + qhi_g) * C_ + (size_t)h * D_;
    #pragma unroll
    for (int j = 0; j < 8; j++) {
        int col = 8 * j + 2 * (lane & 3);
        *(__half2*)(out + rlo + col) = __floats2half2_rn(oacc[j][0] * ilo, oacc[j][1] * ilo);
        *(__half2*)(out + rhi + col) = __floats2half2_rn(oacc[j][2] * ihi, oacc[j][3] * ihi);
    }
}

// ---------------- launch ----------------
extern "C" void kernel_launch(void* const* d_in, const int* in_sizes, int n_in,
                              void* d_out, int out_size)
{
    const float* x   = (const float*)d_in[0];
    const float* Wq  = (const float*)d_in[1];
    const float* Wk  = (const float*)d_in[2];
    const float* Wv  = (const float*)d_in[3];
    const float* Wp  = (const float*)d_in[4];
    const float* bp  = (const float*)d_in[5];
    const float* W1  = (const float*)d_in[6];
    const float* b1  = (const float*)d_in[7];
    const float* W2  = (const float*)d_in[8];
    const float* b2  = (const float*)d_in[9];
    const float* g1  = (const float*)d_in[10];
    const float* be1 = (const float*)d_in[11];
    const float* g2  = (const float*)d_in[12];
    const float* be2 = (const float*)d_in[13];
    float* out = (float*)d_out;

    __half *h1, *qkv, *attn, *h2, *mid, *WqkvT, *WpT, *W1T, *W2T;
    float *y1;
    cudaGetSymbolAddress((void**)&h1,    g_h1);
    cudaGetSymbolAddress((void**)&qkv,   g_qkv);
    cudaGetSymbolAddress((void**)&attn,  g_attn);
    cudaGetSymbolAddress((void**)&y1,    g_y1);
    cudaGetSymbolAddress((void**)&h2,    g_h2);
    cudaGetSymbolAddress((void**)&mid,   g_mid);
    cudaGetSymbolAddress((void**)&WqkvT, g_WqkvT);
    cudaGetSymbolAddress((void**)&WpT,   g_WpT);
    cudaGetSymbolAddress((void**)&W1T,   g_W1T);
    cudaGetSymbolAddress((void**)&W2T,   g_W2T);

    static const int FATTN_SMEM = 3 * 128 * ASTR * (int)sizeof(__half);   // 55296
    static const int GEMM_SMEM  = 2 * 2 * 128 * 144;                       // 73728
    cudaFuncSetAttribute(fattn_kernel, cudaFuncAttributeMaxDynamicSharedMemorySize, FATTN_SMEM);
    cudaFuncSetAttribute(mma_gemm<0, __half>, cudaFuncAttributeMaxDynamicSharedMemorySize, GEMM_SMEM);
    cudaFuncSetAttribute(mma_gemm<2, float>,  cudaFuncAttributeMaxDynamicSharedMemorySize, GEMM_SMEM);
    cudaFuncSetAttribute(mma_gemm<3, __half>, cudaFuncAttributeMaxDynamicSharedMemorySize, GEMM_SMEM);

    // 1. LN1 (fp16 out)
    ln_kernel<<<BT / 4, 128>>>(x, g1, be1, h1);

    // 2. weight repack/transpose to fp16 [N][K]
    repackT_kernel<<<(QKVW * C_ + 255) / 256, 256>>>(Wq, Wk, Wv, WqkvT);
    transpose_kernel<<<dim3(C_ / 32, C_ / 32), dim3(32, 8)>>>(Wp, WpT, C_, C_);
    transpose_kernel<<<dim3(C_ / 32, FF / 32), dim3(32, 8)>>>(W1, W1T, C_, FF);
    transpose_kernel<<<dim3(FF / 32, C_ / 32), dim3(32, 8)>>>(W2, W2T, FF, C_);

    // 3. qkv = h1 @ Wqkv           [32768 x 1152] fp16
    mma_gemm<0, __half><<<dim3(QKVW / 128, BT / 128), 256, GEMM_SMEM>>>(h1, WqkvT, nullptr, nullptr, qkv, BT, QKVW, C_);

    // 4. MMA flash attention       -> attn [32768 x 384] fp16
    fattn_kernel<<<dim3(2, B_ * H_), 256, FATTN_SMEM>>>(qkv, attn);

    // 5. y1 = x + attn @ Wp + bp   fp32
    mma_gemm<2, float><<<dim3(C_ / 128, BT / 128), 256, GEMM_SMEM>>>(attn, WpT, bp, x, y1, BT, C_, C_);

    // 6. LN2 (fp16 out)
    ln_kernel<<<BT / 4, 128>>>(y1, g2, be2, h2);

    // 7. mid = relu(h2 @ W1 + b1)  [32768 x 1536] fp16
    mma_gemm<3, __half><<<dim3(FF / 128, BT / 128), 256, GEMM_SMEM>>>(h2, W1T, b1, nullptr, mid, BT, FF, C_);

    // 8. out = y1 + mid @ W2 + b2  fp32
    mma_gemm<2, float><<<dim3(C_ / 128, BT / 128), 256, GEMM_SMEM>>>(mid, W2T, b2, y1, out, BT, C_, FF);
}

// round 16
// speedup vs baseline: 1.1623x; 1.0336x over previous
#include <cuda_runtime.h>
#include <cuda_fp16.h>
#include <math.h>
#include <stdint.h>

// Problem dims
#define B_  128
#define T_  256
#define C_  384
#define H_  6
#define D_  64
#define BT  (B_*T_)      // 32768 rows
#define FF  (4*C_)       // 1536
#define QKVW (3*C_)      // 1152

// ---------------- scratch (device globals; allocation-free) ----------------
__device__ __half g_h1  [BT*C_];        // LN1 out (fp16)
__device__ __half g_qkv [BT*QKVW];      // q|k|v per row (fp16)
__device__ __half g_attn[BT*C_];        // attention out (fp16)
__device__ float  g_y1  [BT*C_];        // x + attn@Wp + bp
__device__ __half g_h2  [BT*C_];        // LN2 out (fp16)
__device__ __half g_mid [BT*FF];        // relu(h2@W1+b1) (fp16)
__device__ __half g_WqkvT[QKVW*C_];     // QKV weights [n][k] fp16
__device__ __half g_WpT [C_*C_];        // Wp  [n][k] fp16
__device__ __half g_W1T [FF*C_];        // W1  [n][k] fp16
__device__ __half g_W2T [C_*FF];        // W2  [n][k] fp16

// ---------------- PTX helpers ----------------
__device__ __forceinline__ void ldsm_x4(uint32_t* r, uint32_t addr) {
    asm volatile("ldmatrix.sync.aligned.m8n8.x4.shared.b16 {%0,%1,%2,%3}, [%4];"
                 : "=r"(r[0]), "=r"(r[1]), "=r"(r[2]), "=r"(r[3]) : "r"(addr));
}
__device__ __forceinline__ void ldsm_x4t(uint32_t* r, uint32_t addr) {
    asm volatile("ldmatrix.sync.aligned.m8n8.x4.trans.shared.b16 {%0,%1,%2,%3}, [%4];"
                 : "=r"(r[0]), "=r"(r[1]), "=r"(r[2]), "=r"(r[3]) : "r"(addr));
}
__device__ __forceinline__ void ldsm_x2(uint32_t* r, uint32_t addr) {
    asm volatile("ldmatrix.sync.aligned.m8n8.x2.shared.b16 {%0,%1}, [%2];"
                 : "=r"(r[0]), "=r"(r[1]) : "r"(addr));
}
__device__ __forceinline__ void mma_f16(float* c, const uint32_t* a, const uint32_t* b) {
    asm volatile("mma.sync.aligned.m16n8k16.row.col.f32.f16.f16.f32 "
                 "{%0,%1,%2,%3}, {%4,%5,%6,%7}, {%8,%9}, {%0,%1,%2,%3};"
                 : "+f"(c[0]), "+f"(c[1]), "+f"(c[2]), "+f"(c[3])
                 : "r"(a[0]), "r"(a[1]), "r"(a[2]), "r"(a[3]), "r"(b[0]), "r"(b[1]));
}
__device__ __forceinline__ uint32_t pack_h2(float lo, float hi) {
    uint32_t r;
    asm("cvt.rn.f16x2.f32 %0, %1, %2;" : "=r"(r) : "f"(hi), "f"(lo));
    return r;
}
__device__ __forceinline__ void cp16(uint32_t dst, const void* src) {
    asm volatile("cp.async.cg.shared.global [%0], [%1], 16;" :: "r"(dst), "l"(src));
}
#define CP_COMMIT() asm volatile("cp.async.commit_group;" ::: "memory")

// FMA-pipe exp2 for y <= 0 (clamped at -30). Magic-round + deg-4 poly + exponent add.
__device__ __forceinline__ float fexp2(float y) {
    y = fmaxf(y, -30.f);
    float t = y + 12582912.0f;                 // 1.5*2^23: round(y) in low mantissa bits
    int  e = __float_as_int(t) << 23;          // round(y) shifted into exponent position
    float f = y - (t - 12582912.0f);           // f in [-0.5, 0.5]
    float p = 0.00961812911f;
    p = fmaf(p, f, 0.0555041087f);
    p = fmaf(p, f, 0.240226507f);
    p = fmaf(p, f, 0.693147181f);
    p = fmaf(p, f, 1.0f);                      // 2^f, rel err ~4e-5
    return __int_as_float(__float_as_int(p) + e);
}

// ---------------- LayerNorm: one warp per row of 384, fp16 out ----------------
__global__ void ln_kernel(const float* __restrict__ x, const float* __restrict__ g,
                          const float* __restrict__ beta, __half* __restrict__ out)
{
    int row  = blockIdx.x * 4 + (threadIdx.x >> 5);
    int lane = threadIdx.x & 31;
    const float4* xr = (const float4*)(x + (size_t)row * C_);

    float4 v[3];
    float s = 0.f, ss = 0.f;
    #pragma unroll
    for (int i = 0; i < 3; i++) {
        v[i] = xr[lane + i * 32];
        s  += v[i].x + v[i].y + v[i].z + v[i].w;
        ss += v[i].x*v[i].x + v[i].y*v[i].y + v[i].z*v[i].z + v[i].w*v[i].w;
    }
    #pragma unroll
    for (int o = 16; o > 0; o >>= 1) {
        s  += __shfl_xor_sync(0xffffffffu, s,  o);
        ss += __shfl_xor_sync(0xffffffffu, ss, o);
    }
    float mean = s * (1.0f / C_);
    float var  = ss * (1.0f / C_) - mean * mean;
    float rstd = rsqrtf(var + 1e-5f);

    __half* orow = out + (size_t)row * C_;
    #pragma unroll
    for (int i = 0; i < 3; i++) {
        int c = (lane + i * 32) * 4;
        float4 gg = *(const float4*)(g + c);
        float4 bb = *(const float4*)(beta + c);
        float e0 = (v[i].x - mean) * rstd * gg.x + bb.x;
        float e1 = (v[i].y - mean) * rstd * gg.y + bb.y;
        float e2 = (v[i].z - mean) * rstd * gg.z + bb.z;
        float e3 = (v[i].w - mean) * rstd * gg.w + bb.w;
        *(__half2*)(orow + c)     = __floats2half2_rn(e0, e1);
        *(__half2*)(orow + c + 2) = __floats2half2_rn(e2, e3);
    }
}

// ------------- repack Wq/Wk/Wv (H,C,Dh) -> WqkvT[n][k] fp16, n = which*384+h*64+d ----
__global__ void repackT_kernel(const float* __restrict__ Wq, const float* __restrict__ Wk,
                               const float* __restrict__ Wv, __half* __restrict__ WqkvT)
{
    int idx = blockIdx.x * blockDim.x + threadIdx.x;
    if (idx >= QKVW * C_) return;
    int n = idx / C_;
    int k = idx % C_;
    int which = n / C_;
    int nn = n % C_;
    int h = nn / D_, d = nn % D_;
    const float* W = (which == 0) ? Wq : (which == 1) ? Wk : Wv;
    WqkvT[idx] = __float2half_rn(W[(size_t)h * C_ * D_ + (size_t)k * D_ + d]);
}

// ---------------- tiled transpose: W[K][N] fp32 -> Wt[N][K] fp16 ----------------
__global__ void transpose_kernel(const float* __restrict__ W, __half* __restrict__ Wt,
                                 int K, int N)
{
    __shared__ float tile[32][33];
    int kb = blockIdx.x * 32, nb = blockIdx.y * 32;
    int tx = threadIdx.x, ty = threadIdx.y;   // (32, 8)
    #pragma unroll
    for (int i = ty; i < 32; i += 8)
        tile[i][tx] = W[(size_t)(kb + i) * N + nb + tx];
    __syncthreads();
    #pragma unroll
    for (int i = ty; i < 32; i += 8)
        Wt[(size_t)(nb + i) * K + kb + tx] = __float2half_rn(tile[tx][i]);
}

// --------- fp16 tensor-core GEMM: C = A[MxK] * Bt[NxK]^T (+bias)(+res)(+relu) -------
// BM=128 BN=128 BK=32, 256 threads, 3-stage cp.async pipeline (R11 config: best).
template<int EPI, typename OutT>
__global__ void __launch_bounds__(256)
mma_gemm(const __half* __restrict__ A, const __half* __restrict__ Bt,
         const float* __restrict__ bias, const float* __restrict__ res,
         OutT* __restrict__ C, int M, int N, int K)
{
    const int ROWB = 80;                // bytes per padded smem row
    const int TILE = 128 * ROWB;        // 10240
    const int STG  = 2 * TILE;          // A+B per stage = 20480
    extern __shared__ __align__(128) char sbuf[];    // 3 * STG = 61440

    uint32_t sbase = (uint32_t)__cvta_generic_to_shared(sbuf);
    int tid = threadIdx.x, warp = tid >> 5, lane = tid & 31;
    int wm = (warp >> 2) * 64;
    int wn = (warp & 3) * 32;
    int m0 = blockIdx.y * 128, n0 = blockIdx.x * 128;
    int nk = K >> 5;

    float acc[4][4][4];
    #pragma unroll
    for (int i = 0; i < 4; i++)
        #pragma unroll
        for (int j = 0; j < 4; j++)
            #pragma unroll
            for (int r = 0; r < 4; r++) acc[i][j][r] = 0.f;

    uint32_t arow_off[4], brow_off[4];
    #pragma unroll
    for (int mt = 0; mt < 4; mt++)
        arow_off[mt] = (uint32_t)((wm + mt * 16 + (lane & 15)) * ROWB + ((lane & 16) ? 16 : 0));
    #pragma unroll
    for (int nt = 0; nt < 4; nt++)
        brow_off[nt] = (uint32_t)((wn + nt * 8 + (lane & 7)) * ROWB + ((lane & 8) ? 16 : 0));

    auto stage = [&](int t, int buf) {
        int k0 = t << 5;
        uint32_t a_dst = sbase + (uint32_t)buf * STG;
        uint32_t b_dst = a_dst + TILE;
        #pragma unroll
        for (int i = 0; i < 2; i++) {
            int idx = tid + i * 256;
            int r = idx >> 2, cg = idx & 3;
            cp16(a_dst + (uint32_t)(r * ROWB + cg * 16),
                 A + (size_t)(m0 + r) * K + k0 + cg * 8);
        }
        #pragma unroll
        for (int i = 0; i < 2; i++) {
            int idx = tid + i * 256;
            int r = idx >> 2, cg = idx & 3;
            cp16(b_dst + (uint32_t)(r * ROWB + cg * 16),
                 Bt + (size_t)(n0 + r) * K + k0 + cg * 8);
        }
    };

    auto compute = [&](int buf) {
        uint32_t a_base = sbase + (uint32_t)buf * STG;
        uint32_t b_base = a_base + TILE;
        #pragma unroll
        for (int ks = 0; ks < 2; ks++) {
            uint32_t afr[4][4];
            #pragma unroll
            for (int mt = 0; mt < 4; mt++)
                ldsm_x4(afr[mt], a_base + arow_off[mt] + ks * 32u);
            uint32_t bfr[4][2];
            #pragma unroll
            for (int nt = 0; nt < 4; nt++)
                ldsm_x2(bfr[nt], b_base + brow_off[nt] + ks * 32u);
            #pragma unroll
            for (int mt = 0; mt < 4; mt++)
                #pragma unroll
                for (int nt = 0; nt < 4; nt++)
                    mma_f16(acc[mt][nt], afr[mt], bfr[nt]);
        }
    };

    // prologue: 2 stages in flight
    stage(0, 0); CP_COMMIT();
    stage(1, 1); CP_COMMIT();

    int buf = 0;
    for (int t = 0; t < nk; t++) {
        if (t < nk - 1) asm volatile("cp.async.wait_group 1;" ::: "memory");
        else            asm volatile("cp.async.wait_group 0;" ::: "memory");
        __syncthreads();
        if (t + 2 < nk) {
            int nb = buf + 2; if (nb >= 3) nb -= 3;
            stage(t + 2, nb);
            CP_COMMIT();
        }
        compute(buf);
        if (++buf == 3) buf = 0;
    }

    #pragma unroll
    for (int mt = 0; mt < 4; mt++) {
        int row = m0 + wm + mt * 16 + (lane >> 2);
        #pragma unroll
        for (int nt = 0; nt < 4; nt++) {
            int col = n0 + wn + nt * 8 + 2 * (lane & 3);
            float v0 = acc[mt][nt][0], v1 = acc[mt][nt][1];
            float v2 = acc[mt][nt][2], v3 = acc[mt][nt][3];
            if (EPI >= 1) {
                float b0 = bias[col], b1 = bias[col + 1];
                v0 += b0; v1 += b1; v2 += b0; v3 += b1;
            }
            if (EPI == 2) {
                float2 r0 = *(const float2*)(res + (size_t)row * N + col);
                float2 r1 = *(const float2*)(res + (size_t)(row + 8) * N + col);
                v0 += r0.x; v1 += r0.y; v2 += r1.x; v3 += r1.y;
            }
            if (EPI == 3) {
                v0 = fmaxf(v0, 0.f); v1 = fmaxf(v1, 0.f);
                v2 = fmaxf(v2, 0.f); v3 = fmaxf(v3, 0.f);
            }
            if (sizeof(OutT) == 4) {
                *(float2*)((float*)C + (size_t)row * N + col)       = make_float2(v0, v1);
                *(float2*)((float*)C + (size_t)(row + 8) * N + col) = make_float2(v2, v3);
            } else {
                *(__half2*)((__half*)C + (size_t)row * N + col)       = __floats2half2_rn(v0, v1);
                *(__half2*)((__half*)C + (size_t)(row + 8) * N + col) = __floats2half2_rn(v2, v3);
            }
        }
    }
}

// ---------------- MMA flash attention (causal), 64-key chunks, exp2 on FMA pipe ------
// grid = (2 q-tiles, B*H). 256 threads = 8 warps x 16 query rows. 2 CTAs/SM.
// Scores held in log2 domain: scale2 = (1/sqrt(384)) * log2(e).
#define ASTR 72   // smem row stride in halves (144B: conflict-free ldmatrix)
__global__ void __launch_bounds__(256, 2)
fattn_kernel(const __half* __restrict__ qkv, __half* __restrict__ out)
{
    extern __shared__ __half sm[];
    __half* Qs = sm;                  // [128][ASTR]
    __half* Ks = sm + 128 * ASTR;
    __half* Vs = Ks + 128 * ASTR;

    int qt = blockIdx.x;              // 0/1
    int bh = blockIdx.y;
    int b = bh / H_, h = bh % H_;
    int tid = threadIdx.x, warp = tid >> 5, lane = tid & 31;
    int wm = warp * 16;
    int q0 = qt * 128;
    const __half* base = qkv + (size_t)b * T_ * QKVW + (size_t)h * D_;

    uint32_t qs_a = (uint32_t)__cvta_generic_to_shared(Qs);
    uint32_t ks_a = (uint32_t)__cvta_generic_to_shared(Ks);
    uint32_t vs_a = (uint32_t)__cvta_generic_to_shared(Vs);

    // load Q tile (128 x 64 halves)
    for (int i = tid; i < 128 * 8; i += 256) {
        int r = i >> 3, c = i & 7;
        *(float4*)(Qs + r * ASTR + c * 8) =
            *(const float4*)(base + (size_t)(q0 + r) * QKVW + c * 8);
    }

    float mlo = -1e30f, mhi = -1e30f, llo = 0.f, lhi = 0.f;
    float oacc[8][4];
    #pragma unroll
    for (int j = 0; j < 8; j++)
        #pragma unroll
        for (int e = 0; e < 4; e++) oacc[j][e] = 0.f;

    const float scale2 = 0.05103103630798287f * 1.4426950408889634f;  // /sqrt(384) * log2(e)
    int qlo_g = q0 + wm + (lane >> 2);
    int qhi_g = qlo_g + 8;

    uint32_t qf[4][4];

    for (int kt = 0; kt <= qt; kt++) {
        int k0 = kt * 128;
        bool diag = (kt == qt);
        if (kt > 0) __syncthreads();
        for (int i = tid; i < 128 * 8; i += 256) {
            int r = i >> 3, c = i & 7;
            size_t roff = (size_t)(k0 + r) * QKVW + c * 8;
            *(float4*)(Ks + r * ASTR + c * 8) = *(const float4*)(base + C_  + roff);
            *(float4*)(Vs + r * ASTR + c * 8) = *(const float4*)(base + 2*C_ + roff);
        }
        __syncthreads();

        if (kt == 0) {
            #pragma unroll
            for (int kk = 0; kk < 4; kk++)
                ldsm_x4(qf[kk], qs_a + (uint32_t)(((wm + (lane & 15)) * ASTR
                                     + kk * 16 + ((lane >> 4) & 1) * 8) * 2));
        }

        #pragma unroll
        for (int c2 = 0; c2 < 2; c2++) {
            if (diag && c2 == 1 && wm < 64) continue;   // fully-masked chunk
            int kc0 = k0 + c2 * 64;

            float sacc[8][4];
            #pragma unroll
            for (int j = 0; j < 8; j++)
                #pragma unroll
                for (int e = 0; e < 4; e++) sacc[j][e] = 0.f;

            #pragma unroll
            for (int kk = 0; kk < 4; kk++) {
                #pragma unroll
                for (int j2 = 0; j2 < 4; j2++) {
                    uint32_t kb[4];
                    ldsm_x4(kb, ks_a + (uint32_t)(((c2 * 64 + j2 * 16 + ((lane >> 4) & 1) * 8 + (lane & 7)) * ASTR
                                       + kk * 16 + ((lane >> 3) & 1) * 8) * 2));
                    mma_f16(sacc[2*j2],     qf[kk], kb);
                    mma_f16(sacc[2*j2 + 1], qf[kk], kb + 2);
                }
            }

            // ---- scale (log2 domain) + causal mask + row max ----
            float rmlo = -1e30f, rmhi = -1e30f;
            #pragma unroll
            for (int j = 0; j < 8; j++) {
                int key = kc0 + 8 * j + 2 * (lane & 3);
                #pragma unroll
                for (int e = 0; e < 2; e++) {
                    float s = sacc[j][e] * scale2;
                    if (diag && (key + e > qlo_g)) s = -1e30f;
                    sacc[j][e] = s;
                    rmlo = fmaxf(rmlo, s);
                }
                #pragma unroll
                for (int e = 2; e < 4; e++) {
                    float s = sacc[j][e] * scale2;
                    if (diag && (key + e - 2 > qhi_g)) s = -1e30f;
                    sacc[j][e] = s;
                    rmhi = fmaxf(rmhi, s);
                }
            }
            rmlo = fmaxf(rmlo, __shfl_xor_sync(0xffffffffu, rmlo, 1));
            rmlo = fmaxf(rmlo, __shfl_xor_sync(0xffffffffu, rmlo, 2));
            rmhi = fmaxf(rmhi, __shfl_xor_sync(0xffffffffu, rmhi, 1));
            rmhi = fmaxf(rmhi, __shfl_xor_sync(0xffffffffu, rmhi, 2));

            float mnlo = fmaxf(mlo, rmlo), mnhi = fmaxf(mhi, rmhi);
            float elo = fexp2(mlo - mnlo), ehi = fexp2(mhi - mnhi);
            mlo = mnlo; mhi = mnhi;

            // ---- p = 2^(s - m) on the FMA pipe, row sums ----
            float slo = 0.f, shi = 0.f;
            #pragma unroll
            for (int j = 0; j < 8; j++) {
                float p0 = fexp2(sacc[j][0] - mnlo);
                float p1 = fexp2(sacc[j][1] - mnlo);
                float p2 = fexp2(sacc[j][2] - mnhi);
                float p3 = fexp2(sacc[j][3] - mnhi);
                sacc[j][0] = p0; sacc[j][1] = p1; sacc[j][2] = p2; sacc[j][3] = p3;
                slo += p0 + p1; shi += p2 + p3;
            }
            slo += __shfl_xor_sync(0xffffffffu, slo, 1);
            slo += __shfl_xor_sync(0xffffffffu, slo, 2);
            shi += __shfl_xor_sync(0xffffffffu, shi, 1);
            shi += __shfl_xor_sync(0xffffffffu, shi, 2);
            llo = llo * elo + slo;
            lhi = lhi * ehi + shi;

            #pragma unroll
            for (int j = 0; j < 8; j++) {
                oacc[j][0] *= elo; oacc[j][1] *= elo;
                oacc[j][2] *= ehi; oacc[j][3] *= ehi;
            }

            #pragma unroll
            for (int kk2 = 0; kk2 < 4; kk2++) {
                uint32_t pa[4];
                pa[0] = pack_h2(sacc[2*kk2][0],   sacc[2*kk2][1]);
                pa[1] = pack_h2(sacc[2*kk2][2],   sacc[2*kk2][3]);
                pa[2] = pack_h2(sacc[2*kk2+1][0], sacc[2*kk2+1][1]);
                pa[3] = pack_h2(sacc[2*kk2+1][2], sacc[2*kk2+1][3]);
                #pragma unroll
                for (int j2 = 0; j2 < 4; j2++) {
                    uint32_t vb[4];
                    ldsm_x4t(vb, vs_a + (uint32_t)(((c2 * 64 + kk2 * 16 + ((lane >> 3) & 1) * 8 + (lane & 7)) * ASTR
                                        + j2 * 16 + ((lane >> 4) & 1) * 8) * 2));
                    mma_f16(oacc[2*j2],     pa, vb);
                    mma_f16(oacc[2*j2 + 1], pa, vb + 2);
                }
            }
        }
    }

    float ilo = 1.f / llo, ihi = 1.f / lhi;
    size_t rlo = (size_t)(b * T_ + qlo_g) * C_ + (size_t)h * D_;
    size_t rhi = (size_t)(b * T_ + qhi_g) * C_ + (size_t)h * D_;
    #pragma unroll
    for (int j = 0; j < 8; j++) {
        int col = 8 * j + 2 * (lane & 3);
        *(__half2*)(out + rlo + col) = __floats2half2_rn(oacc[j][0] * ilo, oacc[j][1] * ilo);
        *(__half2*)(out + rhi + col) = __floats2half2_rn(oacc[j][2] * ihi, oacc[j][3] * ihi);
    }
}

// ---------------- launch ----------------
extern "C" void kernel_launch(void* const* d_in, const int* in_sizes, int n_in,
                              void* d_out, int out_size)
{
    const float* x   = (const float*)d_in[0];
    const float* Wq  = (const float*)d_in[1];
    const float* Wk  = (const float*)d_in[2];
    const float* Wv  = (const float*)d_in[3];
    const float* Wp  = (const float*)d_in[4];
    const float* bp  = (const float*)d_in[5];
    const float* W1  = (const float*)d_in[6];
    const float* b1  = (const float*)d_in[7];
    const float* W2  = (const float*)d_in[8];
    const float* b2  = (const float*)d_in[9];
    const float* g1  = (const float*)d_in[10];
    const float* be1 = (const float*)d_in[11];
    const float* g2  = (const float*)d_in[12];
    const float* be2 = (const float*)d_in[13];
    float* out = (float*)d_out;

    __half *h1, *qkv, *attn, *h2, *mid, *WqkvT, *WpT, *W1T, *W2T;
    float *y1;
    cudaGetSymbolAddress((void**)&h1,    g_h1);
    cudaGetSymbolAddress((void**)&qkv,   g_qkv);
    cudaGetSymbolAddress((void**)&attn,  g_attn);
    cudaGetSymbolAddress((void**)&y1,    g_y1);
    cudaGetSymbolAddress((void**)&h2,    g_h2);
    cudaGetSymbolAddress((void**)&mid,   g_mid);
    cudaGetSymbolAddress((void**)&WqkvT, g_WqkvT);
    cudaGetSymbolAddress((void**)&WpT,   g_WpT);
    cudaGetSymbolAddress((void**)&W1T,   g_W1T);
    cudaGetSymbolAddress((void**)&W2T,   g_W2T);

    static const int FATTN_SMEM = 3 * 128 * ASTR * (int)sizeof(__half);   // 55296
    static const int GEMM_SMEM  = 3 * 2 * 128 * 80;                        // 61440
    cudaFuncSetAttribute(fattn_kernel, cudaFuncAttributeMaxDynamicSharedMemorySize, FATTN_SMEM);
    cudaFuncSetAttribute(mma_gemm<0, __half>, cudaFuncAttributeMaxDynamicSharedMemorySize, GEMM_SMEM);
    cudaFuncSetAttribute(mma_gemm<2, float>,  cudaFuncAttributeMaxDynamicSharedMemorySize, GEMM_SMEM);
    cudaFuncSetAttribute(mma_gemm<3, __half>, cudaFuncAttributeMaxDynamicSharedMemorySize, GEMM_SMEM);

    // 1. LN1 (fp16 out)
    ln_kernel<<<BT / 4, 128>>>(x, g1, be1, h1);

    // 2. weight repack/transpose to fp16 [N][K]
    repackT_kernel<<<(QKVW * C_ + 255) / 256, 256>>>(Wq, Wk, Wv, WqkvT);
    transpose_kernel<<<dim3(C_ / 32, C_ / 32), dim3(32, 8)>>>(Wp, WpT, C_, C_);
    transpose_kernel<<<dim3(C_ / 32, FF / 32), dim3(32, 8)>>>(W1, W1T, C_, FF);
    transpose_kernel<<<dim3(FF / 32, C_ / 32), dim3(32, 8)>>>(W2, W2T, FF, C_);

    // 3. qkv = h1 @ Wqkv           [32768 x 1152] fp16
    mma_gemm<0, __half><<<dim3(QKVW / 128, BT / 128), 256, GEMM_SMEM>>>(h1, WqkvT, nullptr, nullptr, qkv, BT, QKVW, C_);

    // 4. MMA flash attention       -> attn [32768 x 384] fp16
    fattn_kernel<<<dim3(2, B_ * H_), 256, FATTN_SMEM>>>(qkv, attn);

    // 5. y1 = x + attn @ Wp + bp   fp32
    mma_gemm<2, float><<<dim3(C_ / 128, BT / 128), 256, GEMM_SMEM>>>(attn, WpT, bp, x, y1, BT, C_, C_);

    // 6. LN2 (fp16 out)
    ln_kernel<<<BT / 4, 128>>>(y1, g2, be2, h2);

    // 7. mid = relu(h2 @ W1 + b1)  [32768 x 1536] fp16
    mma_gemm<3, __half><<<dim3(FF / 128, BT / 128), 256, GEMM_SMEM>>>(h2, W1T, b1, nullptr, mid, BT, FF, C_);

    // 8. out = y1 + mid @ W2 + b2  fp32
    mma_gemm<2, float><<<dim3(C_ / 128, BT / 128), 256, GEMM_SMEM>>>(mid, W2T, b2, y1, out, BT, C_, FF);
}

// round 17
// speedup vs baseline: 1.1946x; 1.0277x over previous
#include <cuda_runtime.h>
#include <cuda_fp16.h>
#include <math.h>
#include <stdint.h>

// Problem dims
#define B_  128
#define T_  256
#define C_  384
#define H_  6
#define D_  64
#define BT  (B_*T_)      // 32768 rows
#define FF  (4*C_)       // 1536
#define QKVW (3*C_)      // 1152

// ---------------- scratch (device globals; allocation-free) ----------------
__device__ __half g_h1  [BT*C_];        // LN1 out (fp16)
__device__ __half g_qkv [BT*QKVW];      // q|k|v per row (fp16)
__device__ __half g_attn[BT*C_];        // attention out (fp16)
__device__ float  g_y1  [BT*C_];        // x + attn@Wp + bp
__device__ __half g_h2  [BT*C_];        // LN2 out (fp16)
__device__ __half g_mid [BT*FF];        // relu(h2@W1+b1) (fp16)
__device__ __half g_WqkvT[QKVW*C_];     // QKV weights [n][k] fp16
__device__ __half g_WpT [C_*C_];        // Wp  [n][k] fp16
__device__ __half g_W1T [FF*C_];        // W1  [n][k] fp16
__device__ __half g_W2T [C_*FF];        // W2  [n][k] fp16

// ---------------- PTX helpers ----------------
__device__ __forceinline__ void ldsm_x4(uint32_t* r, uint32_t addr) {
    asm volatile("ldmatrix.sync.aligned.m8n8.x4.shared.b16 {%0,%1,%2,%3}, [%4];"
                 : "=r"(r[0]), "=r"(r[1]), "=r"(r[2]), "=r"(r[3]) : "r"(addr));
}
__device__ __forceinline__ void ldsm_x4t(uint32_t* r, uint32_t addr) {
    asm volatile("ldmatrix.sync.aligned.m8n8.x4.trans.shared.b16 {%0,%1,%2,%3}, [%4];"
                 : "=r"(r[0]), "=r"(r[1]), "=r"(r[2]), "=r"(r[3]) : "r"(addr));
}
__device__ __forceinline__ void ldsm_x2(uint32_t* r, uint32_t addr) {
    asm volatile("ldmatrix.sync.aligned.m8n8.x2.shared.b16 {%0,%1}, [%2];"
                 : "=r"(r[0]), "=r"(r[1]) : "r"(addr));
}
__device__ __forceinline__ void mma_f16(float* c, const uint32_t* a, const uint32_t* b) {
    asm volatile("mma.sync.aligned.m16n8k16.row.col.f32.f16.f16.f32 "
                 "{%0,%1,%2,%3}, {%4,%5,%6,%7}, {%8,%9}, {%0,%1,%2,%3};"
                 : "+f"(c[0]), "+f"(c[1]), "+f"(c[2]), "+f"(c[3])
                 : "r"(a[0]), "r"(a[1]), "r"(a[2]), "r"(a[3]), "r"(b[0]), "r"(b[1]));
}
__device__ __forceinline__ uint32_t pack_h2(float lo, float hi) {
    uint32_t r;
    asm("cvt.rn.f16x2.f32 %0, %1, %2;" : "=r"(r) : "f"(hi), "f"(lo));
    return r;
}
__device__ __forceinline__ void cp16(uint32_t dst, const void* src) {
    asm volatile("cp.async.cg.shared.global [%0], [%1], 16;" :: "r"(dst), "l"(src));
}
#define CP_COMMIT() asm volatile("cp.async.commit_group;" ::: "memory")

// FMA-pipe exp2 for y <= 0 (clamped at -30). Magic-round + deg-4 poly + exponent add.
__device__ __forceinline__ float fexp2(float y) {
    y = fmaxf(y, -30.f);
    float t = y + 12582912.0f;
    int  e = __float_as_int(t) << 23;
    float f = y - (t - 12582912.0f);
    float p = 0.00961812911f;
    p = fmaf(p, f, 0.0555041087f);
    p = fmaf(p, f, 0.240226507f);
    p = fmaf(p, f, 0.693147181f);
    p = fmaf(p, f, 1.0f);
    return __int_as_float(__float_as_int(p) + e);
}

// ---------------- LayerNorm: one warp per row of 384, fp16 out ----------------
__global__ void ln_kernel(const float* __restrict__ x, const float* __restrict__ g,
                          const float* __restrict__ beta, __half* __restrict__ out)
{
    int row  = blockIdx.x * 4 + (threadIdx.x >> 5);
    int lane = threadIdx.x & 31;
    const float4* xr = (const float4*)(x + (size_t)row * C_);

    float4 v[3];
    float s = 0.f, ss = 0.f;
    #pragma unroll
    for (int i = 0; i < 3; i++) {
        v[i] = xr[lane + i * 32];
        s  += v[i].x + v[i].y + v[i].z + v[i].w;
        ss += v[i].x*v[i].x + v[i].y*v[i].y + v[i].z*v[i].z + v[i].w*v[i].w;
    }
    #pragma unroll
    for (int o = 16; o > 0; o >>= 1) {
        s  += __shfl_xor_sync(0xffffffffu, s,  o);
        ss += __shfl_xor_sync(0xffffffffu, ss, o);
    }
    float mean = s * (1.0f / C_);
    float var  = ss * (1.0f / C_) - mean * mean;
    float rstd = rsqrtf(var + 1e-5f);

    __half* orow = out + (size_t)row * C_;
    #pragma unroll
    for (int i = 0; i < 3; i++) {
        int c = (lane + i * 32) * 4;
        float4 gg = *(const float4*)(g + c);
        float4 bb = *(const float4*)(beta + c);
        float e0 = (v[i].x - mean) * rstd * gg.x + bb.x;
        float e1 = (v[i].y - mean) * rstd * gg.y + bb.y;
        float e2 = (v[i].z - mean) * rstd * gg.z + bb.z;
        float e3 = (v[i].w - mean) * rstd * gg.w + bb.w;
        *(__half2*)(orow + c)     = __floats2half2_rn(e0, e1);
        *(__half2*)(orow + c + 2) = __floats2half2_rn(e2, e3);
    }
}

// ---- fused weight prep: repack QKV + transpose Wp/W1/W2, one kernel, 256 thr ----
// blocks [0,1728): repack; [1728,1872): Wp 12x12; [1872,2448): W1 12x48; [2448,3024): W2 48x12
#define PREP_BLOCKS 3024
__global__ void prep_kernel(const float* __restrict__ Wq, const float* __restrict__ Wk,
                            const float* __restrict__ Wv, const float* __restrict__ Wp,
                            const float* __restrict__ W1, const float* __restrict__ W2,
                            __half* __restrict__ WqkvT, __half* __restrict__ WpT,
                            __half* __restrict__ W1T,   __half* __restrict__ W2T)
{
    int bid = blockIdx.x;
    if (bid < 1728) {
        int idx = bid * 256 + threadIdx.x;     // < QKVW*C_ = 442368
        int n = idx / C_;
        int k = idx % C_;
        int which = n / C_;
        int nn = n % C_;
        int h = nn / D_, d = nn % D_;
        const float* W = (which == 0) ? Wq : (which == 1) ? Wk : Wv;
        WqkvT[idx] = __float2half_rn(W[(size_t)h * C_ * D_ + (size_t)k * D_ + d]);
        return;
    }
    int t = bid - 1728;
    const float* W; __half* Wt; int K, N, kb, nb;
    if (t < 144)      { W = Wp; Wt = WpT; K = C_; N = C_;  kb = (t % 12) * 32; nb = (t / 12) * 32; }
    else if (t < 720) { int u = t - 144; W = W1; Wt = W1T; K = C_; N = FF;  kb = (u % 12) * 32; nb = (u / 12) * 32; }
    else              { int u = t - 720; W = W2; Wt = W2T; K = FF; N = C_;  kb = (u % 48) * 32; nb = (u / 48) * 32; }

    __shared__ float tile[32][33];
    int tx = threadIdx.x & 31, ty = threadIdx.x >> 5;   // 8 row-groups
    #pragma unroll
    for (int i = ty; i < 32; i += 8)
        tile[i][tx] = W[(size_t)(kb + i) * N + nb + tx];
    __syncthreads();
    #pragma unroll
    for (int i = ty; i < 32; i += 8)
        Wt[(size_t)(nb + i) * K + kb + tx] = __float2half_rn(tile[tx][i]);
}

// --------- fp16 tensor-core GEMM: C = A[MxK] * Bt[NxK]^T (+bias)(+res)(+relu) -------
// BM=128 BN=128 BK=32, 256 threads, 3-stage cp.async pipeline (R11 config: best).
template<int EPI, typename OutT>
__global__ void __launch_bounds__(256)
mma_gemm(const __half* __restrict__ A, const __half* __restrict__ Bt,
         const float* __restrict__ bias, const float* __restrict__ res,
         OutT* __restrict__ C, int M, int N, int K)
{
    const int ROWB = 80;
    const int TILE = 128 * ROWB;
    const int STG  = 2 * TILE;
    extern __shared__ __align__(128) char sbuf[];

    uint32_t sbase = (uint32_t)__cvta_generic_to_shared(sbuf);
    int tid = threadIdx.x, warp = tid >> 5, lane = tid & 31;
    int wm = (warp >> 2) * 64;
    int wn = (warp & 3) * 32;
    int m0 = blockIdx.y * 128, n0 = blockIdx.x * 128;
    int nk = K >> 5;

    float acc[4][4][4];
    #pragma unroll
    for (int i = 0; i < 4; i++)
        #pragma unroll
        for (int j = 0; j < 4; j++)
            #pragma unroll
            for (int r = 0; r < 4; r++) acc[i][j][r] = 0.f;

    uint32_t arow_off[4], brow_off[4];
    #pragma unroll
    for (int mt = 0; mt < 4; mt++)
        arow_off[mt] = (uint32_t)((wm + mt * 16 + (lane & 15)) * ROWB + ((lane & 16) ? 16 : 0));
    #pragma unroll
    for (int nt = 0; nt < 4; nt++)
        brow_off[nt] = (uint32_t)((wn + nt * 8 + (lane & 7)) * ROWB + ((lane & 8) ? 16 : 0));

    auto stage = [&](int t, int buf) {
        int k0 = t << 5;
        uint32_t a_dst = sbase + (uint32_t)buf * STG;
        uint32_t b_dst = a_dst + TILE;
        #pragma unroll
        for (int i = 0; i < 2; i++) {
            int idx = tid + i * 256;
            int r = idx >> 2, cg = idx & 3;
            cp16(a_dst + (uint32_t)(r * ROWB + cg * 16),
                 A + (size_t)(m0 + r) * K + k0 + cg * 8);
        }
        #pragma unroll
        for (int i = 0; i < 2; i++) {
            int idx = tid + i * 256;
            int r = idx >> 2, cg = idx & 3;
            cp16(b_dst + (uint32_t)(r * ROWB + cg * 16),
                 Bt + (size_t)(n0 + r) * K + k0 + cg * 8);
        }
    };

    auto compute = [&](int buf) {
        uint32_t a_base = sbase + (uint32_t)buf * STG;
        uint32_t b_base = a_base + TILE;
        #pragma unroll
        for (int ks = 0; ks < 2; ks++) {
            uint32_t afr[4][4];
            #pragma unroll
            for (int mt = 0; mt < 4; mt++)
                ldsm_x4(afr[mt], a_base + arow_off[mt] + ks * 32u);
            uint32_t bfr[4][2];
            #pragma unroll
            for (int nt = 0; nt < 4; nt++)
                ldsm_x2(bfr[nt], b_base + brow_off[nt] + ks * 32u);
            #pragma unroll
            for (int mt = 0; mt < 4; mt++)
                #pragma unroll
                for (int nt = 0; nt < 4; nt++)
                    mma_f16(acc[mt][nt], afr[mt], bfr[nt]);
        }
    };

    stage(0, 0); CP_COMMIT();
    stage(1, 1); CP_COMMIT();

    int buf = 0;
    for (int t = 0; t < nk; t++) {
        if (t < nk - 1) asm volatile("cp.async.wait_group 1;" ::: "memory");
        else            asm volatile("cp.async.wait_group 0;" ::: "memory");
        __syncthreads();
        if (t + 2 < nk) {
            int nb = buf + 2; if (nb >= 3) nb -= 3;
            stage(t + 2, nb);
            CP_COMMIT();
        }
        compute(buf);
        if (++buf == 3) buf = 0;
    }

    #pragma unroll
    for (int mt = 0; mt < 4; mt++) {
        int row = m0 + wm + mt * 16 + (lane >> 2);
        #pragma unroll
        for (int nt = 0; nt < 4; nt++) {
            int col = n0 + wn + nt * 8 + 2 * (lane & 3);
            float v0 = acc[mt][nt][0], v1 = acc[mt][nt][1];
            float v2 = acc[mt][nt][2], v3 = acc[mt][nt][3];
            if (EPI >= 1) {
                float b0 = bias[col], b1 = bias[col + 1];
                v0 += b0; v1 += b1; v2 += b0; v3 += b1;
            }
            if (EPI == 2) {
                float2 r0 = *(const float2*)(res + (size_t)row * N + col);
                float2 r1 = *(const float2*)(res + (size_t)(row + 8) * N + col);
                v0 += r0.x; v1 += r0.y; v2 += r1.x; v3 += r1.y;
            }
            if (EPI == 3) {
                v0 = fmaxf(v0, 0.f); v1 = fmaxf(v1, 0.f);
                v2 = fmaxf(v2, 0.f); v3 = fmaxf(v3, 0.f);
            }
            if (sizeof(OutT) == 4) {
                *(float2*)((float*)C + (size_t)row * N + col)       = make_float2(v0, v1);
                *(float2*)((float*)C + (size_t)(row + 8) * N + col) = make_float2(v2, v3);
            } else {
                *(__half2*)((__half*)C + (size_t)row * N + col)       = __floats2half2_rn(v0, v1);
                *(__half2*)((__half*)C + (size_t)(row + 8) * N + col) = __floats2half2_rn(v2, v3);
            }
        }
    }
}

// ---------------- MMA flash attention (causal), merged q-tiles ----------------
// grid = B*H (768 CTAs), 256 threads = 8 warps x 16 query rows, 2 CTAs/SM.
// One CTA handles q-tile 0 AND q-tile 1, reusing the kt=0 K/V smem tile.
#define ASTR 72   // smem row stride in halves (144B: conflict-free ldmatrix)
__global__ void __launch_bounds__(256, 2)
fattn_kernel(const __half* __restrict__ qkv, __half* __restrict__ out)
{
    extern __shared__ __half sm[];
    __half* Qs = sm;                  // [128][ASTR]
    __half* Ks = sm + 128 * ASTR;
    __half* Vs = Ks + 128 * ASTR;

    int bh = blockIdx.x;
    int b = bh / H_, h = bh % H_;
    int tid = threadIdx.x, warp = tid >> 5, lane = tid & 31;
    int wm = warp * 16;
    const __half* base = qkv + (size_t)b * T_ * QKVW + (size_t)h * D_;

    uint32_t qs_a = (uint32_t)__cvta_generic_to_shared(Qs);
    uint32_t ks_a = (uint32_t)__cvta_generic_to_shared(Ks);
    uint32_t vs_a = (uint32_t)__cvta_generic_to_shared(Vs);

    const float scale2 = 0.05103103630798287f * 1.4426950408889634f;  // /sqrt(384) * log2(e)

    float mlo, mhi, llo, lhi;
    float oacc[8][4];
    uint32_t qf[4][4];
    int qlo_g, qhi_g;

    auto load_q = [&](int q0) {
        for (int i = tid; i < 128 * 8; i += 256) {
            int r = i >> 3, c = i & 7;
            *(float4*)(Qs + r * ASTR + c * 8) =
                *(const float4*)(base + (size_t)(q0 + r) * QKVW + c * 8);
        }
    };
    auto load_kv = [&](int k0) {
        for (int i = tid; i < 128 * 8; i += 256) {
            int r = i >> 3, c = i & 7;
            size_t roff = (size_t)(k0 + r) * QKVW + c * 8;
            *(float4*)(Ks + r * ASTR + c * 8) = *(const float4*)(base + C_  + roff);
            *(float4*)(Vs + r * ASTR + c * 8) = *(const float4*)(base + 2*C_ + roff);
        }
    };
    auto load_qf = [&]() {
        #pragma unroll
        for (int kk = 0; kk < 4; kk++)
            ldsm_x4(qf[kk], qs_a + (uint32_t)(((wm + (lane & 15)) * ASTR
                                 + kk * 16 + ((lane >> 4) & 1) * 8) * 2));
    };
    auto reset_state = [&]() {
        mlo = -1e30f; mhi = -1e30f; llo = 0.f; lhi = 0.f;
        #pragma unroll
        for (int j = 0; j < 8; j++)
            #pragma unroll
            for (int e = 0; e < 4; e++) oacc[j][e] = 0.f;
    };

    auto process_tile = [&](int k0, bool diag) {
        #pragma unroll
        for (int c2 = 0; c2 < 2; c2++) {
            if (diag && c2 == 1 && wm < 64) continue;   // fully-masked chunk
            int kc0 = k0 + c2 * 64;

            float sacc[8][4];
            #pragma unroll
            for (int j = 0; j < 8; j++)
                #pragma unroll
                for (int e = 0; e < 4; e++) sacc[j][e] = 0.f;

            #pragma unroll
            for (int kk = 0; kk < 4; kk++) {
                #pragma unroll
                for (int j2 = 0; j2 < 4; j2++) {
                    uint32_t kb[4];
                    ldsm_x4(kb, ks_a + (uint32_t)(((c2 * 64 + j2 * 16 + ((lane >> 4) & 1) * 8 + (lane & 7)) * ASTR
                                       + kk * 16 + ((lane >> 3) & 1) * 8) * 2));
                    mma_f16(sacc[2*j2],     qf[kk], kb);
                    mma_f16(sacc[2*j2 + 1], qf[kk], kb + 2);
                }
            }

            float rmlo = -1e30f, rmhi = -1e30f;
            #pragma unroll
            for (int j = 0; j < 8; j++) {
                int key = kc0 + 8 * j + 2 * (lane & 3);
                #pragma unroll
                for (int e = 0; e < 2; e++) {
                    float s = sacc[j][e] * scale2;
                    if (diag && (key + e > qlo_g)) s = -1e30f;
                    sacc[j][e] = s;
                    rmlo = fmaxf(rmlo, s);
                }
                #pragma unroll
                for (int e = 2; e < 4; e++) {
                    float s = sacc[j][e] * scale2;
                    if (diag && (key + e - 2 > qhi_g)) s = -1e30f;
                    sacc[j][e] = s;
                    rmhi = fmaxf(rmhi, s);
                }
            }
            rmlo = fmaxf(rmlo, __shfl_xor_sync(0xffffffffu, rmlo, 1));
            rmlo = fmaxf(rmlo, __shfl_xor_sync(0xffffffffu, rmlo, 2));
            rmhi = fmaxf(rmhi, __shfl_xor_sync(0xffffffffu, rmhi, 1));
            rmhi = fmaxf(rmhi, __shfl_xor_sync(0xffffffffu, rmhi, 2));

            float mnlo = fmaxf(mlo, rmlo), mnhi = fmaxf(mhi, rmhi);
            float elo = fexp2(mlo - mnlo), ehi = fexp2(mhi - mnhi);
            mlo = mnlo; mhi = mnhi;

            float slo = 0.f, shi = 0.f;
            #pragma unroll
            for (int j = 0; j < 8; j++) {
                float p0 = fexp2(sacc[j][0] - mnlo);
                float p1 = fexp2(sacc[j][1] - mnlo);
                float p2 = fexp2(sacc[j][2] - mnhi);
                float p3 = fexp2(sacc[j][3] - mnhi);
                sacc[j][0] = p0; sacc[j][1] = p1; sacc[j][2] = p2; sacc[j][3] = p3;
                slo += p0 + p1; shi += p2 + p3;
            }
            slo += __shfl_xor_sync(0xffffffffu, slo, 1);
            slo += __shfl_xor_sync(0xffffffffu, slo, 2);
            shi += __shfl_xor_sync(0xffffffffu, shi, 1);
            shi += __shfl_xor_sync(0xffffffffu, shi, 2);
            llo = llo * elo + slo;
            lhi = lhi * ehi + shi;

            #pragma unroll
            for (int j = 0; j < 8; j++) {
                oacc[j][0] *= elo; oacc[j][1] *= elo;
                oacc[j][2] *= ehi; oacc[j][3] *= ehi;
            }

            #pragma unroll
            for (int kk2 = 0; kk2 < 4; kk2++) {
                uint32_t pa[4];
                pa[0] = pack_h2(sacc[2*kk2][0],   sacc[2*kk2][1]);
                pa[1] = pack_h2(sacc[2*kk2][2],   sacc[2*kk2][3]);
                pa[2] = pack_h2(sacc[2*kk2+1][0], sacc[2*kk2+1][1]);
                pa[3] = pack_h2(sacc[2*kk2+1][2], sacc[2*kk2+1][3]);
                #pragma unroll
                for (int j2 = 0; j2 < 4; j2++) {
                    uint32_t vb[4];
                    ldsm_x4t(vb, vs_a + (uint32_t)(((c2 * 64 + kk2 * 16 + ((lane >> 3) & 1) * 8 + (lane & 7)) * ASTR
                                        + j2 * 16 + ((lane >> 4) & 1) * 8) * 2));
                    mma_f16(oacc[2*j2],     pa, vb);
                    mma_f16(oacc[2*j2 + 1], pa, vb + 2);
                }
            }
        }
    };

    auto write_out = [&]() {
        float ilo = 1.f / llo, ihi = 1.f / lhi;
        size_t rlo = (size_t)(b * T_ + qlo_g) * C_ + (size_t)h * D_;
        size_t rhi = (size_t)(b * T_ + qhi_g) * C_ + (size_t)h * D_;
        #pragma unroll
        for (int j = 0; j < 8; j++) {
            int col = 8 * j + 2 * (lane & 3);
            *(__half2*)(out + rlo + col) = __floats2half2_rn(oacc[j][0] * ilo, oacc[j][1] * ilo);
            *(__half2*)(out + rhi + col) = __floats2half2_rn(oacc[j][2] * ihi, oacc[j][3] * ihi);
        }
    };

    // ---- phase A: q-tile 0 (diag vs kt=0) ----
    load_q(0);
    load_kv(0);
    __syncthreads();
    load_qf();
    reset_state();
    qlo_g = wm + (lane >> 2); qhi_g = qlo_g + 8;
    process_tile(0, true);
    write_out();

    // ---- phase B: q-tile 1 (full vs kt=0, then diag vs kt=1) ----
    __syncthreads();                 // everyone done with Qs (qf in regs) before overwrite
    load_q(128);
    __syncthreads();
    load_qf();
    reset_state();
    qlo_g = 128 + wm + (lane >> 2); qhi_g = qlo_g + 8;
    process_tile(0, false);          // kt=0 K/V still resident
    __syncthreads();                 // done reading kt=0 tiles
    load_kv(128);
    __syncthreads();
    process_tile(128, true);
    write_out();
}

// ---------------- launch ----------------
extern "C" void kernel_launch(void* const* d_in, const int* in_sizes, int n_in,
                              void* d_out, int out_size)
{
    const float* x   = (const float*)d_in[0];
    const float* Wq  = (const float*)d_in[1];
    const float* Wk  = (const float*)d_in[2];
    const float* Wv  = (const float*)d_in[3];
    const float* Wp  = (const float*)d_in[4];
    const float* bp  = (const float*)d_in[5];
    const float* W1  = (const float*)d_in[6];
    const float* b1  = (const float*)d_in[7];
    const float* W2  = (const float*)d_in[8];
    const float* b2  = (const float*)d_in[9];
    const float* g1  = (const float*)d_in[10];
    const float* be1 = (const float*)d_in[11];
    const float* g2  = (const float*)d_in[12];
    const float* be2 = (const float*)d_in[13];
    float* out = (float*)d_out;

    __half *h1, *qkv, *attn, *h2, *mid, *WqkvT, *WpT, *W1T, *W2T;
    float *y1;
    cudaGetSymbolAddress((void**)&h1,    g_h1);
    cudaGetSymbolAddress((void**)&qkv,   g_qkv);
    cudaGetSymbolAddress((void**)&attn,  g_attn);
    cudaGetSymbolAddress((void**)&y1,    g_y1);
    cudaGetSymbolAddress((void**)&h2,    g_h2);
    cudaGetSymbolAddress((void**)&mid,   g_mid);
    cudaGetSymbolAddress((void**)&WqkvT, g_WqkvT);
    cudaGetSymbolAddress((void**)&WpT,   g_WpT);
    cudaGetSymbolAddress((void**)&W1T,   g_W1T);
    cudaGetSymbolAddress((void**)&W2T,   g_W2T);

    static const int FATTN_SMEM = 3 * 128 * ASTR * (int)sizeof(__half);   // 55296
    static const int GEMM_SMEM  = 3 * 2 * 128 * 80;                        // 61440
    cudaFuncSetAttribute(fattn_kernel, cudaFuncAttributeMaxDynamicSharedMemorySize, FATTN_SMEM);
    cudaFuncSetAttribute(mma_gemm<0, __half>, cudaFuncAttributeMaxDynamicSharedMemorySize, GEMM_SMEM);
    cudaFuncSetAttribute(mma_gemm<2, float>,  cudaFuncAttributeMaxDynamicSharedMemorySize, GEMM_SMEM);
    cudaFuncSetAttribute(mma_gemm<3, __half>, cudaFuncAttributeMaxDynamicSharedMemorySize, GEMM_SMEM);

    // 1. LN1 (fp16 out)
    ln_kernel<<<BT / 4, 128>>>(x, g1, be1, h1);

    // 2. fused weight prep (repack QKV + transpose Wp/W1/W2)
    prep_kernel<<<PREP_BLOCKS, 256>>>(Wq, Wk, Wv, Wp, W1, W2, WqkvT, WpT, W1T, W2T);

    // 3. qkv = h1 @ Wqkv           [32768 x 1152] fp16
    mma_gemm<0, __half><<<dim3(QKVW / 128, BT / 128), 256, GEMM_SMEM>>>(h1, WqkvT, nullptr, nullptr, qkv, BT, QKVW, C_);

    // 4. MMA flash attention       -> attn [32768 x 384] fp16
    fattn_kernel<<<B_ * H_, 256, FATTN_SMEM>>>(qkv, attn);

    // 5. y1 = x + attn @ Wp + bp   fp32
    mma_gemm<2, float><<<dim3(C_ / 128, BT / 128), 256, GEMM_SMEM>>>(attn, WpT, bp, x, y1, BT, C_, C_);

    // 6. LN2 (fp16 out)
    ln_kernel<<<BT / 4, 128>>>(y1, g2, be2, h2);

    // 7. mid = relu(h2 @ W1 + b1)  [32768 x 1536] fp16
    mma_gemm<3, __half><<<dim3(FF / 128, BT / 128), 256, GEMM_SMEM>>>(h2, W1T, b1, nullptr, mid, BT, FF, C_);

    // 8. out = y1 + mid @ W2 + b2  fp32
    mma_gemm<2, float><<<dim3(C_ / 128, BT / 128), 256, GEMM_SMEM>>>(mid, W2T, b2, y1, out, BT, C_, FF);
}